// round 11
// baseline (speedup 1.0000x reference)
#include <cuda_runtime.h>
#include <cuda_bf16.h>
#include <cstdint>

#define N_NODES 16384
#define KNB 48
#define EDGES (N_NODES * KNB)
#define CV 128
#define IN_DIM 384
#define DW 512
#define LN_EPS 1e-5f

#define STR 136                 // bf16 units; 272B row -> LDSM conflict-free
#define Z_STR 132
#define TBYTES (128 * STR * 2)  // 34816 bytes per tile

typedef unsigned short u16;

// ---------- scratch (allocation-free) ----------
__device__ float g_Spart[(size_t)2 * N_NODES * CV];
__device__ u16  g_aS[N_NODES * CV];
__device__ u16  g_aN[N_NODES * CV];
__device__ float g_v1[N_NODES * CV];
__device__ u16  g_yd[(size_t)N_NODES * DW];
__device__ u16 g_w1em[CV * CV], g_w2m[CV * CV], g_w3m[CV * CV];
__device__ u16 g_w1ee[CV * CV], g_w2e[CV * CV], g_w3e[CV * CV];
__device__ u16 g_dw1[DW * CV], g_dw2[CV * DW];

// ---------- helpers ----------
__device__ __forceinline__ float gelu_f(float x) {
    float y = 0.79788456080286536f * x * (1.0f + 0.044715f * x * x);
    float t; asm("tanh.approx.f32 %0, %1;" : "=f"(t) : "f"(y));
    return 0.5f * x * (1.0f + t);
}
__device__ __forceinline__ __nv_bfloat162 bf2(float a, float b) {
    return __floats2bfloat162_rn(a, b);
}
__device__ __forceinline__ uint32_t smem_u32(const void* p) {
    uint32_t a;
    asm("{ .reg .u64 t; cvta.to.shared.u64 t, %1; cvt.u32.u64 %0, t; }" : "=r"(a) : "l"(p));
    return a;
}
__device__ __forceinline__ void cp16(uint32_t dst, const void* src) {
    asm volatile("cp.async.cg.shared.global [%0], [%1], 16;" :: "r"(dst), "l"(src));
}
#define CP_COMMIT() asm volatile("cp.async.commit_group;")
#define CP_WAIT(n)  asm volatile("cp.async.wait_group %0;" :: "n"(n))

__device__ __forceinline__ void mma16816(float d[4], const unsigned a[4], const unsigned b[2]) {
    asm volatile(
        "mma.sync.aligned.m16n8k16.row.col.f32.bf16.bf16.f32 "
        "{%0,%1,%2,%3}, {%4,%5,%6,%7}, {%8,%9}, {%0,%1,%2,%3};"
        : "+f"(d[0]), "+f"(d[1]), "+f"(d[2]), "+f"(d[3])
        : "r"(a[0]), "r"(a[1]), "r"(a[2]), "r"(a[3]), "r"(b[0]), "r"(b[1]));
}
__device__ __forceinline__ void ldsm4(unsigned& r0, unsigned& r1, unsigned& r2, unsigned& r3,
                                      uint32_t addr) {
    asm volatile("ldmatrix.sync.aligned.m8n8.x4.shared.b16 {%0,%1,%2,%3}, [%4];"
                 : "=r"(r0), "=r"(r1), "=r"(r2), "=r"(r3) : "r"(addr));
}
__device__ __forceinline__ void mma_step(uint32_t aAddr, uint32_t bAddr, float acc[4][4][4]) {
    unsigned a[4][4], b[4][2];
    #pragma unroll
    for (int mi = 0; mi < 4; mi++)
        ldsm4(a[mi][0], a[mi][1], a[mi][2], a[mi][3], aAddr + mi * (16 * STR * 2));
    #pragma unroll
    for (int np = 0; np < 2; np++) {
        unsigned r0, r1, r2, r3;
        ldsm4(r0, r1, r2, r3, bAddr + np * (16 * STR * 2));
        b[2 * np][0] = r0;     b[2 * np][1] = r2;
        b[2 * np + 1][0] = r1; b[2 * np + 1][1] = r3;
    }
    #pragma unroll
    for (int mi = 0; mi < 4; mi++)
        #pragma unroll
        for (int ni = 0; ni < 4; ni++)
            mma16816(acc[mi][ni], a[mi], b[ni]);
}
__device__ __forceinline__ void zero_acc(float acc[4][4][4]) {
    #pragma unroll
    for (int mi = 0; mi < 4; mi++)
        #pragma unroll
        for (int ni = 0; ni < 4; ni++)
            #pragma unroll
            for (int k = 0; k < 4; k++) acc[mi][ni][k] = 0.f;
}
__device__ __forceinline__ uint32_t ldsm_lane_off(int lane, int tile0) {
    return (uint32_t)(((tile0 + (lane & 15)) * STR + ((lane >> 4) << 3)) * 2);
}
__device__ __forceinline__ void stage_w_async(uint32_t dstBase, const u16* __restrict__ W, int tid) {
    #pragma unroll
    for (int e = tid; e < 2048; e += 256) {
        int n = e >> 4, q = e & 15;
        cp16(dstBase + (uint32_t)(n * STR + q * 8) * 2, W + n * CV + q * 8);
    }
}
// row-major in-place epi1: y1 = gelu(raw_y1 + aS[node] + aN[nbr]), coalesced 16B
__device__ __forceinline__ void epi1_rowmajor(u16* B0, int e0, const int* nbrS, int tid) {
    int r = tid >> 1, h = tid & 1;
    int node = (e0 + r) / KNB;
    int nb = nbrS[r];
    u16* yp = &B0[r * STR + h * 64];
    const u16* ap = &g_aS[node * CV + h * 64];
    const u16* np = &g_aN[nb * CV + h * 64];
    #pragma unroll
    for (int t4 = 0; t4 < 8; t4++) {
        uint4 yv = *(uint4*)(yp + t4 * 8);
        uint4 av = *(const uint4*)(ap + t4 * 8);
        uint4 nv = *(const uint4*)(np + t4 * 8);
        unsigned* yw = (unsigned*)&yv;
        unsigned* aw = (unsigned*)&av;
        unsigned* nw = (unsigned*)&nv;
        #pragma unroll
        for (int c2 = 0; c2 < 4; c2++) {
            float2 y = __bfloat1622float2(*(__nv_bfloat162*)&yw[c2]);
            float2 a = __bfloat1622float2(*(__nv_bfloat162*)&aw[c2]);
            float2 n = __bfloat1622float2(*(__nv_bfloat162*)&nw[c2]);
            __nv_bfloat162 o = bf2(gelu_f(y.x + a.x + n.x), gelu_f(y.y + a.y + n.y));
            yw[c2] = *(unsigned*)&o;
        }
        *(uint4*)(yp + t4 * 8) = yv;
    }
}

// ============================================================
// prep conversions
// ============================================================
__global__ void k_cvt3(const float* __restrict__ s2, const float* __restrict__ s3,
                       const float* __restrict__ s1full,
                       u16* __restrict__ d2, u16* __restrict__ d3, u16* __restrict__ d1e)
{
    int i = blockIdx.x * 256 + threadIdx.x;
    int seg = i >> 14, j = i & 16383;
    if (seg == 0)      d2[j] = __bfloat16_as_ushort(__float2bfloat16(s2[j]));
    else if (seg == 1) d3[j] = __bfloat16_as_ushort(__float2bfloat16(s3[j]));
    else {
        int o = j >> 7, c = j & 127;
        d1e[j] = __bfloat16_as_ushort(__float2bfloat16(s1full[o * IN_DIM + CV + c]));
    }
}
__global__ void k_cvtd(const float* __restrict__ w1, const float* __restrict__ w2)
{
    int i = blockIdx.x * 256 + threadIdx.x;
    if (i < 65536) g_dw1[i] = __bfloat16_as_ushort(__float2bfloat16(w1[i]));
    else           g_dw2[i - 65536] = __bfloat16_as_ushort(__float2bfloat16(w2[i - 65536]));
}

// ============================================================
// node precompute
// ============================================================
__global__ void __launch_bounds__(256, 2)
k_nodepre(const float* __restrict__ hVsrc, const float* __restrict__ w1,
          const float* __restrict__ b1, int cg)
{
    extern __shared__ char smx[];
    u16* Xs = (u16*)smx;
    u16* Ws = Xs + 128 * STR;
    const int tid = threadIdx.x;
    const int wp = tid >> 5, lane = tid & 31;
    const int wr0 = (wp & 1) * 64, wc0 = (wp >> 1) * 32;
    const int gr = lane >> 2, ck = (lane & 3) * 2;
    const int r0 = blockIdx.x * 128;
    const int koff = cg ? 2 * CV : 0;
    u16* dst = cg ? g_aN : g_aS;

    for (int e = tid; e < 128 * 32; e += 256) {
        int r = e >> 5, q = e & 31;
        float4 v = *(const float4*)&hVsrc[(r0 + r) * CV + 4 * q];
        __nv_bfloat162 a = bf2(v.x, v.y), b = bf2(v.z, v.w);
        uint2 o = { *(unsigned*)&a, *(unsigned*)&b };
        *(uint2*)&Xs[r * STR + 4 * q] = o;
    }
    for (int e = tid; e < 128 * 32; e += 256) {
        int n = e >> 5, q = e & 31;
        float4 v = *(const float4*)&w1[n * IN_DIM + koff + 4 * q];
        __nv_bfloat162 a = bf2(v.x, v.y), b = bf2(v.z, v.w);
        uint2 o = { *(unsigned*)&a, *(unsigned*)&b };
        *(uint2*)&Ws[n * STR + 4 * q] = o;
    }
    __syncthreads();
    uint32_t aA = smem_u32(Xs) + ldsm_lane_off(lane, wr0);
    uint32_t bA = smem_u32(Ws) + ldsm_lane_off(lane, wc0);
    float acc[4][4][4];
    zero_acc(acc);
    #pragma unroll
    for (int ks = 0; ks < 8; ks++)
        mma_step(aA + ks * 32, bA + ks * 32, acc);
    #pragma unroll
    for (int mi = 0; mi < 4; mi++)
        #pragma unroll
        for (int ni = 0; ni < 4; ni++) {
            int r = wr0 + mi * 16 + gr, c = wc0 + ni * 8 + ck;
            float b0v = cg ? 0.f : b1[c], b1v = cg ? 0.f : b1[c + 1];
            *(__nv_bfloat162*)&dst[(r0 + r) * CV + c] = bf2(acc[mi][ni][0] + b0v, acc[mi][ni][1] + b1v);
            *(__nv_bfloat162*)&dst[(r0 + r + 8) * CV + c] = bf2(acc[mi][ni][2] + b0v, acc[mi][ni][3] + b1v);
        }
}

// ============================================================
// k_fused2 (message): 2-layer MLP per edge, 2-tile smem, 3 CTAs/SM.
// ============================================================
__global__ void __launch_bounds__(256, 3)
k_fused2(const float* __restrict__ hEf, const int* __restrict__ nbr,
         const u16* __restrict__ W1e, const u16* __restrict__ W2,
         const float* __restrict__ b2, const float* __restrict__ maskA)
{
    extern __shared__ char sm[];
    u16* B0 = (u16*)sm;                  // A (both layers)
    u16* B1 = (u16*)(sm + TBYTES);       // W1 -> W2 -> ma*y2 rows
    __shared__ int nbrS[128];
    __shared__ float maS[128];

    const int tid = threadIdx.x;
    const int wp = tid >> 5, lane = tid & 31;
    const int wr0 = (wp & 1) * 64, wc0 = (wp >> 1) * 32;
    const int gr = lane >> 2, ck = (lane & 3) * 2;
    const int e0 = blockIdx.x * 128;

    const uint32_t smb = smem_u32(sm);
    const uint32_t A_addr  = smb + ldsm_lane_off(lane, wr0);
    const uint32_t B1_addr = smb + TBYTES + ldsm_lane_off(lane, wc0);

    stage_w_async(smb + TBYTES, W1e, tid);
    CP_COMMIT();

    // A: hE fp32 -> bf16
    #pragma unroll
    for (int e = tid; e < 128 * 16; e += 256) {
        int r = e >> 4, q = e & 15;
        const float4* src = (const float4*)&hEf[(size_t)(e0 + r) * CV + q * 8];
        float4 v0 = src[0], v1 = src[1];
        __nv_bfloat162 p0 = bf2(v0.x, v0.y), p1 = bf2(v0.z, v0.w);
        __nv_bfloat162 p2 = bf2(v1.x, v1.y), p3 = bf2(v1.z, v1.w);
        uint4 o = { *(unsigned*)&p0, *(unsigned*)&p1, *(unsigned*)&p2, *(unsigned*)&p3 };
        *(uint4*)&B0[r * STR + q * 8] = o;
    }
    if (tid < 128) { nbrS[tid] = nbr[e0 + tid]; maS[tid] = maskA[e0 + tid]; }
    CP_WAIT(0);
    __syncthreads();

    // layer 1
    float acc[4][4][4];
    zero_acc(acc);
    #pragma unroll
    for (int ks = 0; ks < 8; ks++)
        mma_step(A_addr + ks * 32, B1_addr + ks * 32, acc);
    __syncthreads();       // MMA1 reads of B0/B1 done

    // raw y1 -> B0 (frag)
    #pragma unroll
    for (int mi = 0; mi < 4; mi++)
        #pragma unroll
        for (int ni = 0; ni < 4; ni++) {
            int r = wr0 + mi * 16 + gr, c = wc0 + ni * 8 + ck;
            *(__nv_bfloat162*)&B0[r * STR + c] = bf2(acc[mi][ni][0], acc[mi][ni][1]);
            *(__nv_bfloat162*)&B0[(r + 8) * STR + c] = bf2(acc[mi][ni][2], acc[mi][ni][3]);
        }
    // W2 -> B1 (B1 free after sync above)
    stage_w_async(smb + TBYTES, W2, tid);
    CP_COMMIT();
    __syncthreads();       // raw y1 visible
    epi1_rowmajor(B0, e0, nbrS, tid);
    CP_WAIT(0);
    __syncthreads();

    // layer 2
    zero_acc(acc);
    #pragma unroll
    for (int ks = 0; ks < 8; ks++)
        mma_step(A_addr + ks * 32, B1_addr + ks * 32, acc);
    __syncthreads();       // MMA2 reads of B1 done

    // epi2: ma * gelu(acc + b2) -> B1
    #pragma unroll
    for (int mi = 0; mi < 4; mi++)
        #pragma unroll
        for (int ni = 0; ni < 4; ni++) {
            int r = wr0 + mi * 16 + gr, c = wc0 + ni * 8 + ck;
            float b0v = b2[c], b1v = b2[c + 1];
            float ma1 = maS[r], ma2 = maS[r + 8];
            *(__nv_bfloat162*)&B1[r * STR + c] =
                bf2(gelu_f(acc[mi][ni][0] + b0v) * ma1, gelu_f(acc[mi][ni][1] + b1v) * ma1);
            *(__nv_bfloat162*)&B1[(r + 8) * STR + c] =
                bf2(gelu_f(acc[mi][ni][2] + b0v) * ma2, gelu_f(acc[mi][ni][3] + b1v) * ma2);
        }
    __syncthreads();

    // reduce rows per node segment -> g_Spart
    {
        int nd0 = e0 / KNB;
        int ndLast = (e0 + 127) / KNB;
        int nSeg = ndLast - nd0 + 1;
        for (int sc = tid; sc < nSeg * CV; sc += 256) {
            int seg = sc >> 7, c = sc & 127;
            int n = nd0 + seg;
            int rlo = n * KNB;       if (rlo < e0) rlo = e0;
            int rhi = n * KNB + KNB; if (rhi > e0 + 128) rhi = e0 + 128;
            float s = 0.f;
            for (int r = rlo - e0; r < rhi - e0; r++)
                s += __bfloat162float(*(const __nv_bfloat16*)&B1[r * STR + c]);
            int slot = (e0 >> 7) - ((n * KNB) >> 7);
            g_Spart[((size_t)n * 2 + slot) * CV + c] = s;
        }
    }
}

// ============================================================
// k_msgfin: dh = (W3 @ S + (Σma)·b3)/30; g_v1 = LN1(hV + dh)
// ============================================================
__global__ void __launch_bounds__(256, 2)
k_msgfin(const float* __restrict__ hV, const float* __restrict__ b3,
         const float* __restrict__ lnw, const float* __restrict__ lnb,
         const float* __restrict__ maskA)
{
    extern __shared__ char smx[];
    u16* Xs = (u16*)smx;
    float* Zf = (float*)smx;
    __shared__ float smaS[128];
    const uint32_t smb = smem_u32(smx);
    const int tid = threadIdx.x;
    const int wp = tid >> 5, lane = tid & 31;
    const int wr0 = (wp & 1) * 64, wc0 = (wp >> 1) * 32;
    const int gr = lane >> 2, ck = (lane & 3) * 2;
    const int r0 = blockIdx.x * 128;

    stage_w_async(smb + TBYTES, g_w3m, tid);
    CP_COMMIT();

    {
        int r = tid >> 1, h = tid & 1;
        const float* mp = &maskA[(r0 + r) * KNB + h * 24];
        float s = 0.f;
        #pragma unroll
        for (int i = 0; i < 24; i++) s += mp[i];
        s += __shfl_xor_sync(0xffffffffu, s, 1);
        if (h == 0) smaS[r] = s;
    }

    for (int e = tid; e < 128 * 32; e += 256) {
        int r = e >> 5, q = e & 31;
        int n = r0 + r;
        float4 v = *(const float4*)&g_Spart[(size_t)n * 2 * CV + 4 * q];
        if (((n * KNB) & 127) >= 81) {
            float4 w = *(const float4*)&g_Spart[((size_t)n * 2 + 1) * CV + 4 * q];
            v.x += w.x; v.y += w.y; v.z += w.z; v.w += w.w;
        }
        __nv_bfloat162 a = bf2(v.x, v.y), bb = bf2(v.z, v.w);
        uint2 o = { *(unsigned*)&a, *(unsigned*)&bb };
        *(uint2*)&Xs[r * STR + 4 * q] = o;
    }
    CP_WAIT(0);
    __syncthreads();

    uint32_t aA = smb + ldsm_lane_off(lane, wr0);
    uint32_t bA = smb + TBYTES + ldsm_lane_off(lane, wc0);
    float acc[4][4][4];
    zero_acc(acc);
    #pragma unroll
    for (int ks = 0; ks < 8; ks++)
        mma_step(aA + ks * 32, bA + ks * 32, acc);
    __syncthreads();

    #pragma unroll
    for (int mi = 0; mi < 4; mi++)
        #pragma unroll
        for (int ni = 0; ni < 4; ni++) {
            int r = wr0 + mi * 16 + gr, c = wc0 + ni * 8 + ck;
            float b0v = b3[c], b1v = b3[c + 1];
            float sm1 = smaS[r], sm2 = smaS[r + 8];
            float2 h1 = *(const float2*)&hV[(r0 + r) * CV + c];
            float2 h2 = *(const float2*)&hV[(r0 + r + 8) * CV + c];
            *(float2*)&Zf[r * Z_STR + c] = make_float2(
                h1.x + (acc[mi][ni][0] + sm1 * b0v) * (1.0f / 30.0f),
                h1.y + (acc[mi][ni][1] + sm1 * b1v) * (1.0f / 30.0f));
            *(float2*)&Zf[(r + 8) * Z_STR + c] = make_float2(
                h2.x + (acc[mi][ni][2] + sm2 * b0v) * (1.0f / 30.0f),
                h2.y + (acc[mi][ni][3] + sm2 * b1v) * (1.0f / 30.0f));
        }
    __syncthreads();
    {
        int r = tid >> 1, h = tid & 1;
        float s = 0.f, sq = 0.f;
        #pragma unroll 8
        for (int c = h * 64; c < h * 64 + 64; c++) {
            float v = Zf[r * Z_STR + c];
            s += v; sq += v * v;
        }
        s  += __shfl_xor_sync(0xffffffffu, s, 1);
        sq += __shfl_xor_sync(0xffffffffu, sq, 1);
        float mean = s * (1.0f / CV);
        float var  = sq * (1.0f / CV) - mean * mean;
        float inv  = rsqrtf(var + LN_EPS);
        for (int c = h * 64; c < h * 64 + 64; c++) {
            float v = Zf[r * Z_STR + c];
            g_v1[(r0 + r) * CV + c] = (v - mean) * inv * lnw[c] + lnb[c];
        }
    }
}

// ============================================================
// k_fused3 (edge update): 3-layer MLP, 2-tile smem, 3 CTAs/SM.
// ============================================================
__global__ void __launch_bounds__(256, 3)
k_fused3(const float* __restrict__ hEf, const int* __restrict__ nbr,
         const u16* __restrict__ W1e, const u16* __restrict__ W2, const u16* __restrict__ W3,
         const float* __restrict__ b2, const float* __restrict__ b3,
         const float* __restrict__ lnw, const float* __restrict__ lnb,
         float* __restrict__ outE)
{
    extern __shared__ char sm[];
    u16* B0 = (u16*)sm;                  // A (all layers)
    u16* B1 = (u16*)(sm + TBYTES);       // W1 -> W2 -> W3
    float* Zf = (float*)sm;              // LN overlay over both tiles
    __shared__ int nbrS[128];

    const int tid = threadIdx.x;
    const int wp = tid >> 5, lane = tid & 31;
    const int wr0 = (wp & 1) * 64, wc0 = (wp >> 1) * 32;
    const int gr = lane >> 2, ck = (lane & 3) * 2;
    const int e0 = blockIdx.x * 128;

    const uint32_t smb = smem_u32(sm);
    const uint32_t A_addr  = smb + ldsm_lane_off(lane, wr0);
    const uint32_t B1_addr = smb + TBYTES + ldsm_lane_off(lane, wc0);

    stage_w_async(smb + TBYTES, W1e, tid);
    CP_COMMIT();

    #pragma unroll
    for (int e = tid; e < 128 * 16; e += 256) {
        int r = e >> 4, q = e & 15;
        const float4* src = (const float4*)&hEf[(size_t)(e0 + r) * CV + q * 8];
        float4 v0 = src[0], v1 = src[1];
        __nv_bfloat162 p0 = bf2(v0.x, v0.y), p1 = bf2(v0.z, v0.w);
        __nv_bfloat162 p2 = bf2(v1.x, v1.y), p3 = bf2(v1.z, v1.w);
        uint4 o = { *(unsigned*)&p0, *(unsigned*)&p1, *(unsigned*)&p2, *(unsigned*)&p3 };
        *(uint4*)&B0[r * STR + q * 8] = o;
    }
    if (tid < 128) nbrS[tid] = nbr[e0 + tid];
    CP_WAIT(0);
    __syncthreads();

    // layer 1
    float acc[4][4][4];
    zero_acc(acc);
    #pragma unroll
    for (int ks = 0; ks < 8; ks++)
        mma_step(A_addr + ks * 32, B1_addr + ks * 32, acc);
    __syncthreads();

    #pragma unroll
    for (int mi = 0; mi < 4; mi++)
        #pragma unroll
        for (int ni = 0; ni < 4; ni++) {
            int r = wr0 + mi * 16 + gr, c = wc0 + ni * 8 + ck;
            *(__nv_bfloat162*)&B0[r * STR + c] = bf2(acc[mi][ni][0], acc[mi][ni][1]);
            *(__nv_bfloat162*)&B0[(r + 8) * STR + c] = bf2(acc[mi][ni][2], acc[mi][ni][3]);
        }
    stage_w_async(smb + TBYTES, W2, tid);
    CP_COMMIT();
    __syncthreads();
    epi1_rowmajor(B0, e0, nbrS, tid);
    CP_WAIT(0);
    __syncthreads();

    // layer 2
    zero_acc(acc);
    #pragma unroll
    for (int ks = 0; ks < 8; ks++)
        mma_step(A_addr + ks * 32, B1_addr + ks * 32, acc);
    __syncthreads();
    // epi2: gelu(acc + b2) -> B0; W3 -> B1
    #pragma unroll
    for (int mi = 0; mi < 4; mi++)
        #pragma unroll
        for (int ni = 0; ni < 4; ni++) {
            int r = wr0 + mi * 16 + gr, c = wc0 + ni * 8 + ck;
            float b0v = b2[c], b1v = b2[c + 1];
            *(__nv_bfloat162*)&B0[r * STR + c] =
                bf2(gelu_f(acc[mi][ni][0] + b0v), gelu_f(acc[mi][ni][1] + b1v));
            *(__nv_bfloat162*)&B0[(r + 8) * STR + c] =
                bf2(gelu_f(acc[mi][ni][2] + b0v), gelu_f(acc[mi][ni][3] + b1v));
        }
    stage_w_async(smb + TBYTES, W3, tid);
    CP_COMMIT();
    CP_WAIT(0);
    __syncthreads();

    // layer 3
    zero_acc(acc);
    #pragma unroll
    for (int ks = 0; ks < 8; ks++)
        mma_step(A_addr + ks * 32, B1_addr + ks * 32, acc);
    __syncthreads();       // B0/B1 reads done before Zf overlay

    #pragma unroll
    for (int mi = 0; mi < 4; mi++)
        #pragma unroll
        for (int ni = 0; ni < 4; ni++) {
            int r = wr0 + mi * 16 + gr, c = wc0 + ni * 8 + ck;
            float b0v = b3[c], b1v = b3[c + 1];
            float2 res1 = *(const float2*)&hEf[(size_t)(e0 + r) * CV + c];
            float2 res2 = *(const float2*)&hEf[(size_t)(e0 + r + 8) * CV + c];
            *(float2*)&Zf[r * Z_STR + c] =
                make_float2(acc[mi][ni][0] + b0v + res1.x, acc[mi][ni][1] + b1v + res1.y);
            *(float2*)&Zf[(r + 8) * Z_STR + c] =
                make_float2(acc[mi][ni][2] + b0v + res2.x, acc[mi][ni][3] + b1v + res2.y);
        }
    __syncthreads();
    {
        int r = tid >> 1, h = tid & 1;
        float s = 0.f, sq = 0.f;
        #pragma unroll 8
        for (int c = h * 64; c < h * 64 + 64; c++) {
            float v = Zf[r * Z_STR + c];
            s += v; sq += v * v;
        }
        s  += __shfl_xor_sync(0xffffffffu, s, 1);
        sq += __shfl_xor_sync(0xffffffffu, sq, 1);
        float mean = s * (1.0f / CV);
        float var  = sq * (1.0f / CV) - mean * mean;
        float inv  = rsqrtf(var + LN_EPS);
        size_t eg = (size_t)(e0 + r) * CV;
        for (int c = h * 64; c < h * 64 + 64; c++) {
            float v = Zf[r * Z_STR + c];
            outE[eg + c] = (v - mean) * inv * lnw[c] + lnb[c];
        }
    }
}

// ============================================================
// dense1
// ============================================================
__global__ void __launch_bounds__(256, 2)
k_dense1(const float* __restrict__ b)
{
    extern __shared__ char smx[];
    u16* Xs = (u16*)smx;
    const uint32_t smb = smem_u32(smx);
    const int tid = threadIdx.x;
    const int wp = tid >> 5, lane = tid & 31;
    const int wr0 = (wp & 1) * 64, wc0 = (wp >> 1) * 32;
    const int gr = lane >> 2, ck = (lane & 3) * 2;
    const int r0 = blockIdx.x * 128, c0 = blockIdx.y * 128;

    stage_w_async(smb + TBYTES, &g_dw1[c0 * CV], tid);
    CP_COMMIT();
    for (int e = tid; e < 128 * 32; e += 256) {
        int r = e >> 5, q = e & 31;
        float4 v = *(const float4*)&g_v1[(r0 + r) * CV + 4 * q];
        __nv_bfloat162 a = bf2(v.x, v.y), bb = bf2(v.z, v.w);
        uint2 o = { *(unsigned*)&a, *(unsigned*)&bb };
        *(uint2*)&Xs[r * STR + 4 * q] = o;
    }
    CP_WAIT(0);
    __syncthreads();
    uint32_t aA = smb + ldsm_lane_off(lane, wr0);
    uint32_t bA = smb + TBYTES + ldsm_lane_off(lane, wc0);
    float acc[4][4][4];
    zero_acc(acc);
    #pragma unroll
    for (int ks = 0; ks < 8; ks++)
        mma_step(aA + ks * 32, bA + ks * 32, acc);
    #pragma unroll
    for (int mi = 0; mi < 4; mi++)
        #pragma unroll
        for (int ni = 0; ni < 4; ni++) {
            int r = wr0 + mi * 16 + gr, cg = c0 + wc0 + ni * 8 + ck;
            float b0v = b[cg], b1v = b[cg + 1];
            *(__nv_bfloat162*)&g_yd[(size_t)(r0 + r) * DW + cg] =
                bf2(gelu_f(acc[mi][ni][0] + b0v), gelu_f(acc[mi][ni][1] + b1v));
            *(__nv_bfloat162*)&g_yd[(size_t)(r0 + r + 8) * DW + cg] =
                bf2(gelu_f(acc[mi][ni][2] + b0v), gelu_f(acc[mi][ni][3] + b1v));
        }
}

// ============================================================
// dense2
// ============================================================
__device__ __forceinline__ void d2_stage(uint32_t pairBase, int r0, int kt, int tid) {
    #pragma unroll
    for (int e = tid; e < 2048; e += 256) {
        int r = e >> 4, q = e & 15;
        cp16(pairBase + (uint32_t)(r * STR + q * 8) * 2,
             &g_yd[(size_t)(r0 + r) * DW + kt + q * 8]);
    }
    #pragma unroll
    for (int e = tid; e < 2048; e += 256) {
        int n = e >> 4, q = e & 15;
        cp16(pairBase + TBYTES + (uint32_t)(n * STR + q * 8) * 2,
             &g_dw2[n * DW + kt + q * 8]);
    }
    CP_COMMIT();
}

__global__ void __launch_bounds__(256, 1)
k_dense2(const float* __restrict__ b,
         const float* __restrict__ lnw, const float* __restrict__ lnb,
         const float* __restrict__ mask, float* __restrict__ outV)
{
    extern __shared__ char smx[];
    float* Zf = (float*)smx;
    const uint32_t smb = smem_u32(smx);
    const int tid = threadIdx.x;
    const int wp = tid >> 5, lane = tid & 31;
    const int wr0 = (wp & 1) * 64, wc0 = (wp >> 1) * 32;
    const int gr = lane >> 2, ck = (lane & 3) * 2;
    const int r0 = blockIdx.x * 128;

    float acc[4][4][4];
    zero_acc(acc);
    d2_stage(smb, r0, 0, tid);
    #pragma unroll
    for (int i = 0; i < 4; i++) {
        if (i < 3) d2_stage(smb + ((i + 1) & 1) * 2 * TBYTES, r0, (i + 1) * 128, tid);
        if (i < 3) { CP_WAIT(1); } else { CP_WAIT(0); }
        __syncthreads();
        uint32_t pb = smb + (i & 1) * 2 * TBYTES;
        uint32_t aA = pb + ldsm_lane_off(lane, wr0);
        uint32_t bA = pb + TBYTES + ldsm_lane_off(lane, wc0);
        #pragma unroll
        for (int ks = 0; ks < 8; ks++)
            mma_step(aA + ks * 32, bA + ks * 32, acc);
        __syncthreads();
    }
    #pragma unroll
    for (int mi = 0; mi < 4; mi++)
        #pragma unroll
        for (int ni = 0; ni < 4; ni++) {
            int r = wr0 + mi * 16 + gr, c = wc0 + ni * 8 + ck;
            float b0v = b[c], b1v = b[c + 1];
            float2 res1 = *(const float2*)&g_v1[(r0 + r) * CV + c];
            float2 res2 = *(const float2*)&g_v1[(r0 + r + 8) * CV + c];
            *(float2*)&Zf[r * Z_STR + c] =
                make_float2(acc[mi][ni][0] + b0v + res1.x, acc[mi][ni][1] + b1v + res1.y);
            *(float2*)&Zf[(r + 8) * Z_STR + c] =
                make_float2(acc[mi][ni][2] + b0v + res2.x, acc[mi][ni][3] + b1v + res2.y);
        }
    __syncthreads();
    {
        int r = tid >> 1, h = tid & 1;
        float s = 0.f, sq = 0.f;
        #pragma unroll 8
        for (int c = h * 64; c < h * 64 + 64; c++) {
            float v = Zf[r * Z_STR + c];
            s += v; sq += v * v;
        }
        s  += __shfl_xor_sync(0xffffffffu, s, 1);
        sq += __shfl_xor_sync(0xffffffffu, sq, 1);
        float mean = s * (1.0f / CV);
        float var  = sq * (1.0f / CV) - mean * mean;
        float inv  = rsqrtf(var + LN_EPS);
        float mk = mask[r0 + r];
        for (int c = h * 64; c < h * 64 + 64; c++) {
            float v = Zf[r * Z_STR + c];
            outV[(r0 + r) * CV + c] = ((v - mean) * inv * lnw[c] + lnb[c]) * mk;
        }
    }
}

// ============================================================
extern "C" void kernel_launch(void* const* d_in, const int* in_sizes, int n_in,
                              void* d_out, int out_size)
{
    (void)in_sizes; (void)n_in; (void)out_size;
    const float* hV    = (const float*)d_in[0];
    const float* hE    = (const float*)d_in[1];
    const int*   nbr   = (const int*)  d_in[2];
    const float* mask  = (const float*)d_in[3];
    const float* maskA = (const float*)d_in[4];
    const float* msg_w1 = (const float*)d_in[5];
    const float* msg_b1 = (const float*)d_in[6];
    const float* msg_w2 = (const float*)d_in[7];
    const float* msg_b2 = (const float*)d_in[8];
    const float* msg_w3 = (const float*)d_in[9];
    const float* msg_b3 = (const float*)d_in[10];
    const float* ln1_w  = (const float*)d_in[11];
    const float* ln1_b  = (const float*)d_in[12];
    const float* d_w1   = (const float*)d_in[13];
    const float* d_b1   = (const float*)d_in[14];
    const float* d_w2   = (const float*)d_in[15];
    const float* d_b2   = (const float*)d_in[16];
    const float* ln2_w  = (const float*)d_in[17];
    const float* ln2_b  = (const float*)d_in[18];
    const float* eu_w1  = (const float*)d_in[19];
    const float* eu_b1  = (const float*)d_in[20];
    const float* eu_w2  = (const float*)d_in[21];
    const float* eu_b2  = (const float*)d_in[22];
    const float* eu_w3  = (const float*)d_in[23];
    const float* eu_b3  = (const float*)d_in[24];
    const float* ln3_w  = (const float*)d_in[25];
    const float* ln3_b  = (const float*)d_in[26];

    float* outV = (float*)d_out;
    float* outE = outV + (size_t)N_NODES * CV;

    u16 *p_w2m, *p_w3m, *p_w2e, *p_w3e, *p_w1em, *p_w1ee;
    cudaGetSymbolAddress((void**)&p_w2m, g_w2m);
    cudaGetSymbolAddress((void**)&p_w3m, g_w3m);
    cudaGetSymbolAddress((void**)&p_w2e, g_w2e);
    cudaGetSymbolAddress((void**)&p_w3e, g_w3e);
    cudaGetSymbolAddress((void**)&p_w1em, g_w1em);
    cudaGetSymbolAddress((void**)&p_w1ee, g_w1ee);

    const int SMEM_F  = 2 * TBYTES;   // 69632 -> 3 CTAs/SM
    const int SMEM_G  = 2 * TBYTES;   // 69632
    const int SMEM_D2 = 4 * TBYTES;   // 139264
    cudaFuncSetAttribute(k_fused2,  cudaFuncAttributeMaxDynamicSharedMemorySize, SMEM_F);
    cudaFuncSetAttribute(k_fused3,  cudaFuncAttributeMaxDynamicSharedMemorySize, SMEM_F);
    cudaFuncSetAttribute(k_msgfin,  cudaFuncAttributeMaxDynamicSharedMemorySize, SMEM_G);
    cudaFuncSetAttribute(k_nodepre, cudaFuncAttributeMaxDynamicSharedMemorySize, SMEM_G);
    cudaFuncSetAttribute(k_dense1,  cudaFuncAttributeMaxDynamicSharedMemorySize, SMEM_G);
    cudaFuncSetAttribute(k_dense2,  cudaFuncAttributeMaxDynamicSharedMemorySize, SMEM_D2);

    const int EGRID = EDGES / 128;  // 6144

    k_cvt3<<<192, 256>>>(msg_w2, msg_w3, msg_w1, p_w2m, p_w3m, p_w1em);   // 1
    k_cvt3<<<192, 256>>>(eu_w2,  eu_w3,  eu_w1,  p_w2e, p_w3e, p_w1ee);   // 2
    k_cvtd<<<512, 256>>>(d_w1, d_w2);                                     // 3
    k_nodepre<<<N_NODES / 128, 256, SMEM_G>>>(hV, msg_w1, msg_b1, 0);     // 4
    k_nodepre<<<N_NODES / 128, 256, SMEM_G>>>(hV, msg_w1, msg_b1, 1);     // 5
    k_fused2<<<EGRID, 256, SMEM_F>>>(hE, nbr, p_w1em, p_w2m,              // 6 <- profiled
                                     msg_b2, maskA);
    k_msgfin<<<N_NODES / 128, 256, SMEM_G>>>(hV, msg_b3, ln1_w, ln1_b, maskA);
    k_dense1<<<dim3(N_NODES / 128, 4), 256, SMEM_G>>>(d_b1);
    k_dense2<<<N_NODES / 128, 256, SMEM_D2>>>(d_b2, ln2_w, ln2_b, mask, outV);
    k_nodepre<<<N_NODES / 128, 256, SMEM_G>>>(outV, eu_w1, eu_b1, 0);
    k_nodepre<<<N_NODES / 128, 256, SMEM_G>>>(outV, eu_w1, eu_b1, 1);
    k_fused3<<<EGRID, 256, SMEM_F>>>(hE, nbr, p_w1ee, p_w2e, p_w3e,
                                     eu_b2, eu_b3, ln3_w, ln3_b, outE);
}

// round 12
// speedup vs baseline: 1.2246x; 1.2246x over previous
#include <cuda_runtime.h>
#include <cuda_bf16.h>
#include <cstdint>

#define N_NODES 16384
#define KNB 48
#define EDGES (N_NODES * KNB)
#define CV 128
#define IN_DIM 384
#define DW 512
#define LN_EPS 1e-5f

#define STR 136                 // bf16 units; 272B row -> LDSM conflict-free
#define Z_STR 132
#define TBYTES (128 * STR * 2)  // 34816 bytes per tile

typedef unsigned short u16;

// ---------- scratch (allocation-free) ----------
__device__ float g_Spart[(size_t)2 * N_NODES * CV];
__device__ u16  g_aS[N_NODES * CV];
__device__ u16  g_aN[N_NODES * CV];
__device__ float g_v1[N_NODES * CV];
__device__ u16  g_yd[(size_t)N_NODES * DW];
__device__ u16 g_w1em[CV * CV], g_w2m[CV * CV], g_w3m[CV * CV];
__device__ u16 g_w1ee[CV * CV], g_w2e[CV * CV], g_w3e[CV * CV];
__device__ u16 g_dw1[DW * CV], g_dw2[CV * DW];

// ---------- helpers ----------
__device__ __forceinline__ float gelu_f(float x) {
    float y = 0.79788456080286536f * x * (1.0f + 0.044715f * x * x);
    float t; asm("tanh.approx.f32 %0, %1;" : "=f"(t) : "f"(y));
    return 0.5f * x * (1.0f + t);
}
__device__ __forceinline__ __nv_bfloat162 bf2(float a, float b) {
    return __floats2bfloat162_rn(a, b);
}
__device__ __forceinline__ uint32_t smem_u32(const void* p) {
    uint32_t a;
    asm("{ .reg .u64 t; cvta.to.shared.u64 t, %1; cvt.u32.u64 %0, t; }" : "=r"(a) : "l"(p));
    return a;
}
__device__ __forceinline__ void cp16(uint32_t dst, const void* src) {
    asm volatile("cp.async.cg.shared.global [%0], [%1], 16;" :: "r"(dst), "l"(src));
}
#define CP_COMMIT() asm volatile("cp.async.commit_group;")
#define CP_WAIT(n)  asm volatile("cp.async.wait_group %0;" :: "n"(n))

__device__ __forceinline__ void mma16816(float d[4], const unsigned a[4], const unsigned b[2]) {
    asm volatile(
        "mma.sync.aligned.m16n8k16.row.col.f32.bf16.bf16.f32 "
        "{%0,%1,%2,%3}, {%4,%5,%6,%7}, {%8,%9}, {%0,%1,%2,%3};"
        : "+f"(d[0]), "+f"(d[1]), "+f"(d[2]), "+f"(d[3])
        : "r"(a[0]), "r"(a[1]), "r"(a[2]), "r"(a[3]), "r"(b[0]), "r"(b[1]));
}
__device__ __forceinline__ void ldsm4(unsigned& r0, unsigned& r1, unsigned& r2, unsigned& r3,
                                      uint32_t addr) {
    asm volatile("ldmatrix.sync.aligned.m8n8.x4.shared.b16 {%0,%1,%2,%3}, [%4];"
                 : "=r"(r0), "=r"(r1), "=r"(r2), "=r"(r3) : "r"(addr));
}
__device__ __forceinline__ void mma_step(uint32_t aAddr, uint32_t bAddr, float acc[4][4][4]) {
    unsigned a[4][4], b[4][2];
    #pragma unroll
    for (int mi = 0; mi < 4; mi++)
        ldsm4(a[mi][0], a[mi][1], a[mi][2], a[mi][3], aAddr + mi * (16 * STR * 2));
    #pragma unroll
    for (int np = 0; np < 2; np++) {
        unsigned r0, r1, r2, r3;
        ldsm4(r0, r1, r2, r3, bAddr + np * (16 * STR * 2));
        b[2 * np][0] = r0;     b[2 * np][1] = r2;
        b[2 * np + 1][0] = r1; b[2 * np + 1][1] = r3;
    }
    #pragma unroll
    for (int mi = 0; mi < 4; mi++)
        #pragma unroll
        for (int ni = 0; ni < 4; ni++)
            mma16816(acc[mi][ni], a[mi], b[ni]);
}
__device__ __forceinline__ void zero_acc(float acc[4][4][4]) {
    #pragma unroll
    for (int mi = 0; mi < 4; mi++)
        #pragma unroll
        for (int ni = 0; ni < 4; ni++)
            #pragma unroll
            for (int k = 0; k < 4; k++) acc[mi][ni][k] = 0.f;
}
__device__ __forceinline__ uint32_t ldsm_lane_off(int lane, int tile0) {
    return (uint32_t)(((tile0 + (lane & 15)) * STR + ((lane >> 4) << 3)) * 2);
}
__device__ __forceinline__ void stage_w_async(uint32_t dstBase, const u16* __restrict__ W, int tid) {
    #pragma unroll
    for (int e = tid; e < 2048; e += 256) {
        int n = e >> 4, q = e & 15;
        cp16(dstBase + (uint32_t)(n * STR + q * 8) * 2, W + n * CV + q * 8);
    }
}

// fragment-layout epi1: y1 = gelu(acc + aS[node] + aN[nbr]) -> tile A (bf16)
// ebase = global edge index of A's row 0; acc holds raw layer-1 output.
__device__ __forceinline__ void epi1_frag(u16* A, int ebase, const int* nbrS, int nbrBase,
                                          float acc[4][4][4],
                                          int wr0, int wc0, int gr, int ck) {
    uint32_t offS[8], offN[8];
    #pragma unroll
    for (int mi = 0; mi < 4; mi++)
        #pragma unroll
        for (int hh = 0; hh < 2; hh++) {
            int r = wr0 + mi * 16 + gr + hh * 8;
            int j = mi * 2 + hh;
            offS[j] = (uint32_t)(((ebase + r) / KNB) * CV) * 2;
            offN[j] = (uint32_t)(nbrS[nbrBase + r] * CV) * 2;
        }
    const char* aSb = (const char*)g_aS;
    const char* aNb = (const char*)g_aN;
    #pragma unroll
    for (int mi = 0; mi < 4; mi++)
        #pragma unroll
        for (int ni = 0; ni < 4; ni++) {
            int c = wc0 + ni * 8 + ck;
            #pragma unroll
            for (int hh = 0; hh < 2; hh++) {
                int j = mi * 2 + hh;
                unsigned as = *(const unsigned*)(aSb + offS[j] + c * 2);
                unsigned an = *(const unsigned*)(aNb + offN[j] + c * 2);
                float2 a = __bfloat1622float2(*(__nv_bfloat162*)&as);
                float2 n = __bfloat1622float2(*(__nv_bfloat162*)&an);
                float v0 = acc[mi][ni][2 * hh]     + a.x + n.x;
                float v1 = acc[mi][ni][2 * hh + 1] + a.y + n.y;
                int r = wr0 + mi * 16 + gr + hh * 8;
                *(__nv_bfloat162*)&A[r * STR + c] = bf2(gelu_f(v0), gelu_f(v1));
            }
        }
}

// ============================================================
// prep conversions
// ============================================================
__global__ void k_cvt3(const float* __restrict__ s2, const float* __restrict__ s3,
                       const float* __restrict__ s1full,
                       u16* __restrict__ d2, u16* __restrict__ d3, u16* __restrict__ d1e)
{
    int i = blockIdx.x * 256 + threadIdx.x;
    int seg = i >> 14, j = i & 16383;
    if (seg == 0)      d2[j] = __bfloat16_as_ushort(__float2bfloat16(s2[j]));
    else if (seg == 1) d3[j] = __bfloat16_as_ushort(__float2bfloat16(s3[j]));
    else {
        int o = j >> 7, c = j & 127;
        d1e[j] = __bfloat16_as_ushort(__float2bfloat16(s1full[o * IN_DIM + CV + c]));
    }
}
__global__ void k_cvtd(const float* __restrict__ w1, const float* __restrict__ w2)
{
    int i = blockIdx.x * 256 + threadIdx.x;
    if (i < 65536) g_dw1[i] = __bfloat16_as_ushort(__float2bfloat16(w1[i]));
    else           g_dw2[i - 65536] = __bfloat16_as_ushort(__float2bfloat16(w2[i - 65536]));
}

// ============================================================
// node precompute
// ============================================================
__global__ void __launch_bounds__(256, 2)
k_nodepre(const float* __restrict__ hVsrc, const float* __restrict__ w1,
          const float* __restrict__ b1, int cg)
{
    extern __shared__ char smx[];
    u16* Xs = (u16*)smx;
    u16* Ws = Xs + 128 * STR;
    const int tid = threadIdx.x;
    const int wp = tid >> 5, lane = tid & 31;
    const int wr0 = (wp & 1) * 64, wc0 = (wp >> 1) * 32;
    const int gr = lane >> 2, ck = (lane & 3) * 2;
    const int r0 = blockIdx.x * 128;
    const int koff = cg ? 2 * CV : 0;
    u16* dst = cg ? g_aN : g_aS;

    for (int e = tid; e < 128 * 32; e += 256) {
        int r = e >> 5, q = e & 31;
        float4 v = *(const float4*)&hVsrc[(r0 + r) * CV + 4 * q];
        __nv_bfloat162 a = bf2(v.x, v.y), b = bf2(v.z, v.w);
        uint2 o = { *(unsigned*)&a, *(unsigned*)&b };
        *(uint2*)&Xs[r * STR + 4 * q] = o;
    }
    for (int e = tid; e < 128 * 32; e += 256) {
        int n = e >> 5, q = e & 31;
        float4 v = *(const float4*)&w1[n * IN_DIM + koff + 4 * q];
        __nv_bfloat162 a = bf2(v.x, v.y), b = bf2(v.z, v.w);
        uint2 o = { *(unsigned*)&a, *(unsigned*)&b };
        *(uint2*)&Ws[n * STR + 4 * q] = o;
    }
    __syncthreads();
    uint32_t aA = smem_u32(Xs) + ldsm_lane_off(lane, wr0);
    uint32_t bA = smem_u32(Ws) + ldsm_lane_off(lane, wc0);
    float acc[4][4][4];
    zero_acc(acc);
    #pragma unroll
    for (int ks = 0; ks < 8; ks++)
        mma_step(aA + ks * 32, bA + ks * 32, acc);
    #pragma unroll
    for (int mi = 0; mi < 4; mi++)
        #pragma unroll
        for (int ni = 0; ni < 4; ni++) {
            int r = wr0 + mi * 16 + gr, c = wc0 + ni * 8 + ck;
            float b0v = cg ? 0.f : b1[c], b1v = cg ? 0.f : b1[c + 1];
            *(__nv_bfloat162*)&dst[(r0 + r) * CV + c] = bf2(acc[mi][ni][0] + b0v, acc[mi][ni][1] + b1v);
            *(__nv_bfloat162*)&dst[(r0 + r + 8) * CV + c] = bf2(acc[mi][ni][2] + b0v, acc[mi][ni][3] + b1v);
        }
}

// ============================================================
// k_fused2 (message): 2-layer MLP, 256 edge rows / block (2 chunks),
// shared W buffer; epilogue reduces rows per node -> g_Spart.
// ============================================================
__global__ void __launch_bounds__(256, 2)
k_fused2(const float* __restrict__ hEf, const int* __restrict__ nbr,
         const u16* __restrict__ W1e, const u16* __restrict__ W2,
         const float* __restrict__ b2, const float* __restrict__ maskA)
{
    extern __shared__ char sm[];
    u16* A0 = (u16*)sm;
    u16* A1 = (u16*)(sm + TBYTES);
    __shared__ int nbrS[256];
    __shared__ float maS[256];

    const int tid = threadIdx.x;
    const int wp = tid >> 5, lane = tid & 31;
    const int wr0 = (wp & 1) * 64, wc0 = (wp >> 1) * 32;
    const int gr = lane >> 2, ck = (lane & 3) * 2;
    const int e0 = blockIdx.x * 256;

    const uint32_t smb = smem_u32(sm);
    const uint32_t A0_addr = smb + ldsm_lane_off(lane, wr0);
    const uint32_t A1_addr = smb + TBYTES + ldsm_lane_off(lane, wr0);
    const uint32_t W_addr  = smb + 2 * TBYTES + ldsm_lane_off(lane, wc0);
    const uint32_t W_base  = smb + 2 * TBYTES;

    stage_w_async(W_base, W1e, tid);
    CP_COMMIT();

    // A0/A1: hE fp32 -> bf16
    #pragma unroll
    for (int e = tid; e < 256 * 16; e += 256) {
        int r = e >> 4, q = e & 15;
        const float4* src = (const float4*)&hEf[(size_t)(e0 + r) * CV + q * 8];
        float4 v0 = src[0], v1 = src[1];
        __nv_bfloat162 p0 = bf2(v0.x, v0.y), p1 = bf2(v0.z, v0.w);
        __nv_bfloat162 p2 = bf2(v1.x, v1.y), p3 = bf2(v1.z, v1.w);
        uint4 o = { *(unsigned*)&p0, *(unsigned*)&p1, *(unsigned*)&p2, *(unsigned*)&p3 };
        u16* dst = (r < 128) ? &A0[r * STR + q * 8] : &A1[(r - 128) * STR + q * 8];
        *(uint4*)dst = o;
    }
    nbrS[tid] = nbr[e0 + tid];
    maS[tid]  = maskA[e0 + tid];
    CP_WAIT(0);
    __syncthreads();

    float acc[4][4][4];

    // ---- layer 1, chunk 0 ----
    zero_acc(acc);
    #pragma unroll
    for (int ks = 0; ks < 8; ks++)
        mma_step(A0_addr + ks * 32, W_addr + ks * 32, acc);
    __syncthreads();                      // A0/W reads done (chunk0)
    epi1_frag(A0, e0, nbrS, 0, acc, wr0, wc0, gr, ck);

    // ---- layer 1, chunk 1 ----
    zero_acc(acc);
    #pragma unroll
    for (int ks = 0; ks < 8; ks++)
        mma_step(A1_addr + ks * 32, W_addr + ks * 32, acc);
    __syncthreads();                      // A1/W reads done -> W free; epi1(A0) visible
    stage_w_async(W_base, W2, tid);       // overlap W2 with epi1(A1)
    CP_COMMIT();
    epi1_frag(A1, e0 + 128, nbrS, 128, acc, wr0, wc0, gr, ck);
    CP_WAIT(0);
    __syncthreads();                      // W2 ready; epi1(A1) visible

    // ---- layer 2, chunk 0 ----
    zero_acc(acc);
    #pragma unroll
    for (int ks = 0; ks < 8; ks++)
        mma_step(A0_addr + ks * 32, W_addr + ks * 32, acc);
    __syncthreads();                      // A0 reads done
    // epi2 chunk0: ma * gelu(acc + b2) -> A0
    #pragma unroll
    for (int mi = 0; mi < 4; mi++)
        #pragma unroll
        for (int ni = 0; ni < 4; ni++) {
            int r = wr0 + mi * 16 + gr, c = wc0 + ni * 8 + ck;
            float b0v = b2[c], b1v = b2[c + 1];
            float ma1 = maS[r], ma2 = maS[r + 8];
            *(__nv_bfloat162*)&A0[r * STR + c] =
                bf2(gelu_f(acc[mi][ni][0] + b0v) * ma1, gelu_f(acc[mi][ni][1] + b1v) * ma1);
            *(__nv_bfloat162*)&A0[(r + 8) * STR + c] =
                bf2(gelu_f(acc[mi][ni][2] + b0v) * ma2, gelu_f(acc[mi][ni][3] + b1v) * ma2);
        }

    // ---- layer 2, chunk 1 ----
    zero_acc(acc);
    #pragma unroll
    for (int ks = 0; ks < 8; ks++)
        mma_step(A1_addr + ks * 32, W_addr + ks * 32, acc);
    __syncthreads();                      // A1 reads done; epi2(A0) visible
    #pragma unroll
    for (int mi = 0; mi < 4; mi++)
        #pragma unroll
        for (int ni = 0; ni < 4; ni++) {
            int r = wr0 + mi * 16 + gr, c = wc0 + ni * 8 + ck;
            float b0v = b2[c], b1v = b2[c + 1];
            float ma1 = maS[128 + r], ma2 = maS[128 + r + 8];
            *(__nv_bfloat162*)&A1[r * STR + c] =
                bf2(gelu_f(acc[mi][ni][0] + b0v) * ma1, gelu_f(acc[mi][ni][1] + b1v) * ma1);
            *(__nv_bfloat162*)&A1[(r + 8) * STR + c] =
                bf2(gelu_f(acc[mi][ni][2] + b0v) * ma2, gelu_f(acc[mi][ni][3] + b1v) * ma2);
        }
    __syncthreads();

    // reduce 256 rows per node segment -> g_Spart (256-row block slots)
    {
        int nd0 = e0 / KNB;
        int ndLast = (e0 + 255) / KNB;
        int nSeg = ndLast - nd0 + 1;
        for (int sc = tid; sc < nSeg * CV; sc += 256) {
            int seg = sc >> 7, c = sc & 127;
            int n = nd0 + seg;
            int rlo = n * KNB;       if (rlo < e0) rlo = e0;
            int rhi = n * KNB + KNB; if (rhi > e0 + 256) rhi = e0 + 256;
            float s = 0.f;
            int l0 = rlo - e0, l1 = rhi - e0;
            int m0 = l1 < 128 ? l1 : 128;
            for (int r = l0; r < m0; r++)
                s += __bfloat162float(*(const __nv_bfloat16*)&A0[r * STR + c]);
            int m1 = l0 > 128 ? l0 : 128;
            for (int r = m1; r < l1; r++)
                s += __bfloat162float(*(const __nv_bfloat16*)&A1[(r - 128) * STR + c]);
            int slot = (e0 >> 8) - ((n * KNB) >> 8);
            g_Spart[((size_t)n * 2 + slot) * CV + c] = s;
        }
    }
}

// ============================================================
// k_msgfin: dh = (W3 @ S + (Σma)·b3)/30; g_v1 = LN1(hV + dh)
// ============================================================
__global__ void __launch_bounds__(256, 2)
k_msgfin(const float* __restrict__ hV, const float* __restrict__ b3,
         const float* __restrict__ lnw, const float* __restrict__ lnb,
         const float* __restrict__ maskA)
{
    extern __shared__ char smx[];
    u16* Xs = (u16*)smx;
    float* Zf = (float*)smx;
    __shared__ float smaS[128];
    const uint32_t smb = smem_u32(smx);
    const int tid = threadIdx.x;
    const int wp = tid >> 5, lane = tid & 31;
    const int wr0 = (wp & 1) * 64, wc0 = (wp >> 1) * 32;
    const int gr = lane >> 2, ck = (lane & 3) * 2;
    const int r0 = blockIdx.x * 128;

    stage_w_async(smb + TBYTES, g_w3m, tid);
    CP_COMMIT();

    {
        int r = tid >> 1, h = tid & 1;
        const float* mp = &maskA[(r0 + r) * KNB + h * 24];
        float s = 0.f;
        #pragma unroll
        for (int i = 0; i < 24; i++) s += mp[i];
        s += __shfl_xor_sync(0xffffffffu, s, 1);
        if (h == 0) smaS[r] = s;
    }

    for (int e = tid; e < 128 * 32; e += 256) {
        int r = e >> 5, q = e & 31;
        int n = r0 + r;
        float4 v = *(const float4*)&g_Spart[(size_t)n * 2 * CV + 4 * q];
        if (((n * KNB) & 255) >= 209) {   // node crosses a 256-row block boundary
            float4 w = *(const float4*)&g_Spart[((size_t)n * 2 + 1) * CV + 4 * q];
            v.x += w.x; v.y += w.y; v.z += w.z; v.w += w.w;
        }
        __nv_bfloat162 a = bf2(v.x, v.y), bb = bf2(v.z, v.w);
        uint2 o = { *(unsigned*)&a, *(unsigned*)&bb };
        *(uint2*)&Xs[r * STR + 4 * q] = o;
    }
    CP_WAIT(0);
    __syncthreads();

    uint32_t aA = smb + ldsm_lane_off(lane, wr0);
    uint32_t bA = smb + TBYTES + ldsm_lane_off(lane, wc0);
    float acc[4][4][4];
    zero_acc(acc);
    #pragma unroll
    for (int ks = 0; ks < 8; ks++)
        mma_step(aA + ks * 32, bA + ks * 32, acc);
    __syncthreads();

    #pragma unroll
    for (int mi = 0; mi < 4; mi++)
        #pragma unroll
        for (int ni = 0; ni < 4; ni++) {
            int r = wr0 + mi * 16 + gr, c = wc0 + ni * 8 + ck;
            float b0v = b3[c], b1v = b3[c + 1];
            float sm1 = smaS[r], sm2 = smaS[r + 8];
            float2 h1 = *(const float2*)&hV[(r0 + r) * CV + c];
            float2 h2 = *(const float2*)&hV[(r0 + r + 8) * CV + c];
            *(float2*)&Zf[r * Z_STR + c] = make_float2(
                h1.x + (acc[mi][ni][0] + sm1 * b0v) * (1.0f / 30.0f),
                h1.y + (acc[mi][ni][1] + sm1 * b1v) * (1.0f / 30.0f));
            *(float2*)&Zf[(r + 8) * Z_STR + c] = make_float2(
                h2.x + (acc[mi][ni][2] + sm2 * b0v) * (1.0f / 30.0f),
                h2.y + (acc[mi][ni][3] + sm2 * b1v) * (1.0f / 30.0f));
        }
    __syncthreads();
    {
        int r = tid >> 1, h = tid & 1;
        float s = 0.f, sq = 0.f;
        #pragma unroll 8
        for (int c = h * 64; c < h * 64 + 64; c++) {
            float v = Zf[r * Z_STR + c];
            s += v; sq += v * v;
        }
        s  += __shfl_xor_sync(0xffffffffu, s, 1);
        sq += __shfl_xor_sync(0xffffffffu, sq, 1);
        float mean = s * (1.0f / CV);
        float var  = sq * (1.0f / CV) - mean * mean;
        float inv  = rsqrtf(var + LN_EPS);
        for (int c = h * 64; c < h * 64 + 64; c++) {
            float v = Zf[r * Z_STR + c];
            g_v1[(r0 + r) * CV + c] = (v - mean) * inv * lnw[c] + lnb[c];
        }
    }
}

// ============================================================
// k_fused3 (edge update): 3-layer MLP + residual + LN3 -> outE  (R10 layout)
// ============================================================
__global__ void __launch_bounds__(256, 2)
k_fused3(const float* __restrict__ hEf, const int* __restrict__ nbr,
         const u16* __restrict__ W1e, const u16* __restrict__ W2, const u16* __restrict__ W3,
         const float* __restrict__ b2, const float* __restrict__ b3,
         const float* __restrict__ lnw, const float* __restrict__ lnb,
         float* __restrict__ outE)
{
    extern __shared__ char sm[];
    u16* B0 = (u16*)sm;
    float* Zf = (float*)(sm + TBYTES);
    __shared__ int nbrS[128];

    const int tid = threadIdx.x;
    const int wp = tid >> 5, lane = tid & 31;
    const int wr0 = (wp & 1) * 64, wc0 = (wp >> 1) * 32;
    const int gr = lane >> 2, ck = (lane & 3) * 2;
    const int e0 = blockIdx.x * 128;

    const uint32_t smb = smem_u32(sm);
    const uint32_t A_addr  = smb + ldsm_lane_off(lane, wr0);
    const uint32_t B1_addr = smb + TBYTES + ldsm_lane_off(lane, wc0);
    const uint32_t B2_addr = smb + 2 * TBYTES + ldsm_lane_off(lane, wc0);

    stage_w_async(smb + TBYTES, W1e, tid);
    CP_COMMIT();
    stage_w_async(smb + 2 * TBYTES, W2, tid);
    CP_COMMIT();

    #pragma unroll
    for (int e = tid; e < 128 * 16; e += 256) {
        int r = e >> 4, q = e & 15;
        const float4* src = (const float4*)&hEf[(size_t)(e0 + r) * CV + q * 8];
        float4 v0 = src[0], v1 = src[1];
        __nv_bfloat162 p0 = bf2(v0.x, v0.y), p1 = bf2(v0.z, v0.w);
        __nv_bfloat162 p2 = bf2(v1.x, v1.y), p3 = bf2(v1.z, v1.w);
        uint4 o = { *(unsigned*)&p0, *(unsigned*)&p1, *(unsigned*)&p2, *(unsigned*)&p3 };
        *(uint4*)&B0[r * STR + q * 8] = o;
    }
    if (tid < 128) nbrS[tid] = nbr[e0 + tid];
    CP_WAIT(1);
    __syncthreads();

    float acc[4][4][4];
    zero_acc(acc);
    #pragma unroll
    for (int ks = 0; ks < 8; ks++)
        mma_step(A_addr + ks * 32, B1_addr + ks * 32, acc);
    __syncthreads();

    epi1_frag(B0, e0, nbrS, 0, acc, wr0, wc0, gr, ck);
    stage_w_async(smb + TBYTES, W3, tid);
    CP_COMMIT();
    CP_WAIT(1);
    __syncthreads();

    zero_acc(acc);
    #pragma unroll
    for (int ks = 0; ks < 8; ks++)
        mma_step(A_addr + ks * 32, B2_addr + ks * 32, acc);
    __syncthreads();
    #pragma unroll
    for (int mi = 0; mi < 4; mi++)
        #pragma unroll
        for (int ni = 0; ni < 4; ni++) {
            int r = wr0 + mi * 16 + gr, c = wc0 + ni * 8 + ck;
            float b0v = b2[c], b1v = b2[c + 1];
            *(__nv_bfloat162*)&B0[r * STR + c] =
                bf2(gelu_f(acc[mi][ni][0] + b0v), gelu_f(acc[mi][ni][1] + b1v));
            *(__nv_bfloat162*)&B0[(r + 8) * STR + c] =
                bf2(gelu_f(acc[mi][ni][2] + b0v), gelu_f(acc[mi][ni][3] + b1v));
        }
    CP_WAIT(0);
    __syncthreads();

    zero_acc(acc);
    #pragma unroll
    for (int ks = 0; ks < 8; ks++)
        mma_step(A_addr + ks * 32, B1_addr + ks * 32, acc);

    __syncthreads();
    #pragma unroll
    for (int mi = 0; mi < 4; mi++)
        #pragma unroll
        for (int ni = 0; ni < 4; ni++) {
            int r = wr0 + mi * 16 + gr, c = wc0 + ni * 8 + ck;
            float b0v = b3[c], b1v = b3[c + 1];
            float2 res1 = *(const float2*)&hEf[(size_t)(e0 + r) * CV + c];
            float2 res2 = *(const float2*)&hEf[(size_t)(e0 + r + 8) * CV + c];
            *(float2*)&Zf[r * Z_STR + c] =
                make_float2(acc[mi][ni][0] + b0v + res1.x, acc[mi][ni][1] + b1v + res1.y);
            *(float2*)&Zf[(r + 8) * Z_STR + c] =
                make_float2(acc[mi][ni][2] + b0v + res2.x, acc[mi][ni][3] + b1v + res2.y);
        }
    __syncthreads();
    {
        int r = tid >> 1, h = tid & 1;
        float s = 0.f, sq = 0.f;
        #pragma unroll 8
        for (int c = h * 64; c < h * 64 + 64; c++) {
            float v = Zf[r * Z_STR + c];
            s += v; sq += v * v;
        }
        s  += __shfl_xor_sync(0xffffffffu, s, 1);
        sq += __shfl_xor_sync(0xffffffffu, sq, 1);
        float mean = s * (1.0f / CV);
        float var  = sq * (1.0f / CV) - mean * mean;
        float inv  = rsqrtf(var + LN_EPS);
        size_t eg = (size_t)(e0 + r) * CV;
        for (int c = h * 64; c < h * 64 + 64; c++) {
            float v = Zf[r * Z_STR + c];
            outE[eg + c] = (v - mean) * inv * lnw[c] + lnb[c];
        }
    }
}

// ============================================================
// dense1
// ============================================================
__global__ void __launch_bounds__(256, 2)
k_dense1(const float* __restrict__ b)
{
    extern __shared__ char smx[];
    u16* Xs = (u16*)smx;
    const uint32_t smb = smem_u32(smx);
    const int tid = threadIdx.x;
    const int wp = tid >> 5, lane = tid & 31;
    const int wr0 = (wp & 1) * 64, wc0 = (wp >> 1) * 32;
    const int gr = lane >> 2, ck = (lane & 3) * 2;
    const int r0 = blockIdx.x * 128, c0 = blockIdx.y * 128;

    stage_w_async(smb + TBYTES, &g_dw1[c0 * CV], tid);
    CP_COMMIT();
    for (int e = tid; e < 128 * 32; e += 256) {
        int r = e >> 5, q = e & 31;
        float4 v = *(const float4*)&g_v1[(r0 + r) * CV + 4 * q];
        __nv_bfloat162 a = bf2(v.x, v.y), bb = bf2(v.z, v.w);
        uint2 o = { *(unsigned*)&a, *(unsigned*)&bb };
        *(uint2*)&Xs[r * STR + 4 * q] = o;
    }
    CP_WAIT(0);
    __syncthreads();
    uint32_t aA = smb + ldsm_lane_off(lane, wr0);
    uint32_t bA = smb + TBYTES + ldsm_lane_off(lane, wc0);
    float acc[4][4][4];
    zero_acc(acc);
    #pragma unroll
    for (int ks = 0; ks < 8; ks++)
        mma_step(aA + ks * 32, bA + ks * 32, acc);
    #pragma unroll
    for (int mi = 0; mi < 4; mi++)
        #pragma unroll
        for (int ni = 0; ni < 4; ni++) {
            int r = wr0 + mi * 16 + gr, cg = c0 + wc0 + ni * 8 + ck;
            float b0v = b[cg], b1v = b[cg + 1];
            *(__nv_bfloat162*)&g_yd[(size_t)(r0 + r) * DW + cg] =
                bf2(gelu_f(acc[mi][ni][0] + b0v), gelu_f(acc[mi][ni][1] + b1v));
            *(__nv_bfloat162*)&g_yd[(size_t)(r0 + r + 8) * DW + cg] =
                bf2(gelu_f(acc[mi][ni][2] + b0v), gelu_f(acc[mi][ni][3] + b1v));
        }
}

// ============================================================
// dense2
// ============================================================
__device__ __forceinline__ void d2_stage(uint32_t pairBase, int r0, int kt, int tid) {
    #pragma unroll
    for (int e = tid; e < 2048; e += 256) {
        int r = e >> 4, q = e & 15;
        cp16(pairBase + (uint32_t)(r * STR + q * 8) * 2,
             &g_yd[(size_t)(r0 + r) * DW + kt + q * 8]);
    }
    #pragma unroll
    for (int e = tid; e < 2048; e += 256) {
        int n = e >> 4, q = e & 15;
        cp16(pairBase + TBYTES + (uint32_t)(n * STR + q * 8) * 2,
             &g_dw2[n * DW + kt + q * 8]);
    }
    CP_COMMIT();
}

__global__ void __launch_bounds__(256, 1)
k_dense2(const float* __restrict__ b,
         const float* __restrict__ lnw, const float* __restrict__ lnb,
         const float* __restrict__ mask, float* __restrict__ outV)
{
    extern __shared__ char smx[];
    float* Zf = (float*)smx;
    const uint32_t smb = smem_u32(smx);
    const int tid = threadIdx.x;
    const int wp = tid >> 5, lane = tid & 31;
    const int wr0 = (wp & 1) * 64, wc0 = (wp >> 1) * 32;
    const int gr = lane >> 2, ck = (lane & 3) * 2;
    const int r0 = blockIdx.x * 128;

    float acc[4][4][4];
    zero_acc(acc);
    d2_stage(smb, r0, 0, tid);
    #pragma unroll
    for (int i = 0; i < 4; i++) {
        if (i < 3) d2_stage(smb + ((i + 1) & 1) * 2 * TBYTES, r0, (i + 1) * 128, tid);
        if (i < 3) { CP_WAIT(1); } else { CP_WAIT(0); }
        __syncthreads();
        uint32_t pb = smb + (i & 1) * 2 * TBYTES;
        uint32_t aA = pb + ldsm_lane_off(lane, wr0);
        uint32_t bA = pb + TBYTES + ldsm_lane_off(lane, wc0);
        #pragma unroll
        for (int ks = 0; ks < 8; ks++)
            mma_step(aA + ks * 32, bA + ks * 32, acc);
        __syncthreads();
    }
    #pragma unroll
    for (int mi = 0; mi < 4; mi++)
        #pragma unroll
        for (int ni = 0; ni < 4; ni++) {
            int r = wr0 + mi * 16 + gr, c = wc0 + ni * 8 + ck;
            float b0v = b[c], b1v = b[c + 1];
            float2 res1 = *(const float2*)&g_v1[(r0 + r) * CV + c];
            float2 res2 = *(const float2*)&g_v1[(r0 + r + 8) * CV + c];
            *(float2*)&Zf[r * Z_STR + c] =
                make_float2(acc[mi][ni][0] + b0v + res1.x, acc[mi][ni][1] + b1v + res1.y);
            *(float2*)&Zf[(r + 8) * Z_STR + c] =
                make_float2(acc[mi][ni][2] + b0v + res2.x, acc[mi][ni][3] + b1v + res2.y);
        }
    __syncthreads();
    {
        int r = tid >> 1, h = tid & 1;
        float s = 0.f, sq = 0.f;
        #pragma unroll 8
        for (int c = h * 64; c < h * 64 + 64; c++) {
            float v = Zf[r * Z_STR + c];
            s += v; sq += v * v;
        }
        s  += __shfl_xor_sync(0xffffffffu, s, 1);
        sq += __shfl_xor_sync(0xffffffffu, sq, 1);
        float mean = s * (1.0f / CV);
        float var  = sq * (1.0f / CV) - mean * mean;
        float inv  = rsqrtf(var + LN_EPS);
        float mk = mask[r0 + r];
        for (int c = h * 64; c < h * 64 + 64; c++) {
            float v = Zf[r * Z_STR + c];
            outV[(r0 + r) * CV + c] = ((v - mean) * inv * lnw[c] + lnb[c]) * mk;
        }
    }
}

// ============================================================
extern "C" void kernel_launch(void* const* d_in, const int* in_sizes, int n_in,
                              void* d_out, int out_size)
{
    (void)in_sizes; (void)n_in; (void)out_size;
    const float* hV    = (const float*)d_in[0];
    const float* hE    = (const float*)d_in[1];
    const int*   nbr   = (const int*)  d_in[2];
    const float* mask  = (const float*)d_in[3];
    const float* maskA = (const float*)d_in[4];
    const float* msg_w1 = (const float*)d_in[5];
    const float* msg_b1 = (const float*)d_in[6];
    const float* msg_w2 = (const float*)d_in[7];
    const float* msg_b2 = (const float*)d_in[8];
    const float* msg_w3 = (const float*)d_in[9];
    const float* msg_b3 = (const float*)d_in[10];
    const float* ln1_w  = (const float*)d_in[11];
    const float* ln1_b  = (const float*)d_in[12];
    const float* d_w1   = (const float*)d_in[13];
    const float* d_b1   = (const float*)d_in[14];
    const float* d_w2   = (const float*)d_in[15];
    const float* d_b2   = (const float*)d_in[16];
    const float* ln2_w  = (const float*)d_in[17];
    const float* ln2_b  = (const float*)d_in[18];
    const float* eu_w1  = (const float*)d_in[19];
    const float* eu_b1  = (const float*)d_in[20];
    const float* eu_w2  = (const float*)d_in[21];
    const float* eu_b2  = (const float*)d_in[22];
    const float* eu_w3  = (const float*)d_in[23];
    const float* eu_b3  = (const float*)d_in[24];
    const float* ln3_w  = (const float*)d_in[25];
    const float* ln3_b  = (const float*)d_in[26];

    float* outV = (float*)d_out;
    float* outE = outV + (size_t)N_NODES * CV;

    u16 *p_w2m, *p_w3m, *p_w2e, *p_w3e, *p_w1em, *p_w1ee;
    cudaGetSymbolAddress((void**)&p_w2m, g_w2m);
    cudaGetSymbolAddress((void**)&p_w3m, g_w3m);
    cudaGetSymbolAddress((void**)&p_w2e, g_w2e);
    cudaGetSymbolAddress((void**)&p_w3e, g_w3e);
    cudaGetSymbolAddress((void**)&p_w1em, g_w1em);
    cudaGetSymbolAddress((void**)&p_w1ee, g_w1ee);

    const int SMEM_F  = 3 * TBYTES;   // 104448
    const int SMEM_G  = 2 * TBYTES;   // 69632
    const int SMEM_D2 = 4 * TBYTES;   // 139264
    cudaFuncSetAttribute(k_fused2,  cudaFuncAttributeMaxDynamicSharedMemorySize, SMEM_F);
    cudaFuncSetAttribute(k_fused3,  cudaFuncAttributeMaxDynamicSharedMemorySize, SMEM_F);
    cudaFuncSetAttribute(k_msgfin,  cudaFuncAttributeMaxDynamicSharedMemorySize, SMEM_G);
    cudaFuncSetAttribute(k_nodepre, cudaFuncAttributeMaxDynamicSharedMemorySize, SMEM_G);
    cudaFuncSetAttribute(k_dense1,  cudaFuncAttributeMaxDynamicSharedMemorySize, SMEM_G);
    cudaFuncSetAttribute(k_dense2,  cudaFuncAttributeMaxDynamicSharedMemorySize, SMEM_D2);

    k_cvt3<<<192, 256>>>(msg_w2, msg_w3, msg_w1, p_w2m, p_w3m, p_w1em);   // 1
    k_cvt3<<<192, 256>>>(eu_w2,  eu_w3,  eu_w1,  p_w2e, p_w3e, p_w1ee);   // 2
    k_cvtd<<<512, 256>>>(d_w1, d_w2);                                     // 3
    k_nodepre<<<N_NODES / 128, 256, SMEM_G>>>(hV, msg_w1, msg_b1, 0);     // 4
    k_nodepre<<<N_NODES / 128, 256, SMEM_G>>>(hV, msg_w1, msg_b1, 1);     // 5
    k_fused2<<<EDGES / 256, 256, SMEM_F>>>(hE, nbr, p_w1em, p_w2m,        // 6 <- profiled
                                           msg_b2, maskA);
    k_msgfin<<<N_NODES / 128, 256, SMEM_G>>>(hV, msg_b3, ln1_w, ln1_b, maskA);
    k_dense1<<<dim3(N_NODES / 128, 4), 256, SMEM_G>>>(d_b1);
    k_dense2<<<N_NODES / 128, 256, SMEM_D2>>>(d_b2, ln2_w, ln2_b, mask, outV);
    k_nodepre<<<N_NODES / 128, 256, SMEM_G>>>(outV, eu_w1, eu_b1, 0);
    k_nodepre<<<N_NODES / 128, 256, SMEM_G>>>(outV, eu_w1, eu_b1, 1);
    k_fused3<<<EDGES / 128, 256, SMEM_F>>>(hE, nbr, p_w1ee, p_w2e, p_w3e,
                                           eu_b2, eu_b3, ln3_w, ln3_b, outE);
}

// round 13
// speedup vs baseline: 1.9169x; 1.5654x over previous
#include <cuda_runtime.h>
#include <cuda_bf16.h>
#include <cstdint>

#define N_NODES 16384
#define KNB 48
#define EDGES (N_NODES * KNB)
#define CV 128
#define IN_DIM 384
#define DW 512
#define LN_EPS 1e-5f

#define STR 136                 // bf16 units; 272B row -> LDSM conflict-free
#define Z_STR 132
#define TBYTES (128 * STR * 2)  // 34816 bytes per tile

typedef unsigned short u16;

// ---------- scratch (allocation-free) ----------
__device__ float g_Spart[(size_t)2 * N_NODES * CV];
__device__ u16  g_aS[N_NODES * CV];
__device__ u16  g_aN[N_NODES * CV];
__device__ float g_v1[N_NODES * CV];
__device__ u16  g_yd[(size_t)N_NODES * DW];
__device__ u16 g_w1em[CV * CV], g_w2m[CV * CV], g_w3m[CV * CV];
__device__ u16 g_w1ee[CV * CV], g_w2e[CV * CV], g_w3e[CV * CV];
__device__ u16 g_dw1[DW * CV], g_dw2[CV * DW];

// ---------- helpers ----------
__device__ __forceinline__ float gelu_f(float x) {
    float y = 0.79788456080286536f * x * (1.0f + 0.044715f * x * x);
    float t; asm("tanh.approx.f32 %0, %1;" : "=f"(t) : "f"(y));
    return 0.5f * x * (1.0f + t);
}
__device__ __forceinline__ __nv_bfloat162 bf2(float a, float b) {
    return __floats2bfloat162_rn(a, b);
}
__device__ __forceinline__ uint32_t smem_u32(const void* p) {
    uint32_t a;
    asm("{ .reg .u64 t; cvta.to.shared.u64 t, %1; cvt.u32.u64 %0, t; }" : "=r"(a) : "l"(p));
    return a;
}
__device__ __forceinline__ void cp16(uint32_t dst, const void* src) {
    asm volatile("cp.async.cg.shared.global [%0], [%1], 16;" :: "r"(dst), "l"(src));
}
#define CP_COMMIT() asm volatile("cp.async.commit_group;")
#define CP_WAIT(n)  asm volatile("cp.async.wait_group %0;" :: "n"(n))

__device__ __forceinline__ void mma16816(float d[4], const unsigned a[4], const unsigned b[2]) {
    asm volatile(
        "mma.sync.aligned.m16n8k16.row.col.f32.bf16.bf16.f32 "
        "{%0,%1,%2,%3}, {%4,%5,%6,%7}, {%8,%9}, {%0,%1,%2,%3};"
        : "+f"(d[0]), "+f"(d[1]), "+f"(d[2]), "+f"(d[3])
        : "r"(a[0]), "r"(a[1]), "r"(a[2]), "r"(a[3]), "r"(b[0]), "r"(b[1]));
}
__device__ __forceinline__ void ldsm4(unsigned& r0, unsigned& r1, unsigned& r2, unsigned& r3,
                                      uint32_t addr) {
    asm volatile("ldmatrix.sync.aligned.m8n8.x4.shared.b16 {%0,%1,%2,%3}, [%4];"
                 : "=r"(r0), "=r"(r1), "=r"(r2), "=r"(r3) : "r"(addr));
}
__device__ __forceinline__ void mma_step(uint32_t aAddr, uint32_t bAddr, float acc[4][4][4]) {
    unsigned a[4][4], b[4][2];
    #pragma unroll
    for (int mi = 0; mi < 4; mi++)
        ldsm4(a[mi][0], a[mi][1], a[mi][2], a[mi][3], aAddr + mi * (16 * STR * 2));
    #pragma unroll
    for (int np = 0; np < 2; np++) {
        unsigned r0, r1, r2, r3;
        ldsm4(r0, r1, r2, r3, bAddr + np * (16 * STR * 2));
        b[2 * np][0] = r0;     b[2 * np][1] = r2;
        b[2 * np + 1][0] = r1; b[2 * np + 1][1] = r3;
    }
    #pragma unroll
    for (int mi = 0; mi < 4; mi++)
        #pragma unroll
        for (int ni = 0; ni < 4; ni++)
            mma16816(acc[mi][ni], a[mi], b[ni]);
}
__device__ __forceinline__ void zero_acc(float acc[4][4][4]) {
    #pragma unroll
    for (int mi = 0; mi < 4; mi++)
        #pragma unroll
        for (int ni = 0; ni < 4; ni++)
            #pragma unroll
            for (int k = 0; k < 4; k++) acc[mi][ni][k] = 0.f;
}
__device__ __forceinline__ uint32_t ldsm_lane_off(int lane, int tile0) {
    return (uint32_t)(((tile0 + (lane & 15)) * STR + ((lane >> 4) << 3)) * 2);
}
__device__ __forceinline__ void stage_w_async(uint32_t dstBase, const u16* __restrict__ W, int tid) {
    #pragma unroll
    for (int e = tid; e < 2048; e += 256) {
        int n = e >> 4, q = e & 15;
        cp16(dstBase + (uint32_t)(n * STR + q * 8) * 2, W + n * CV + q * 8);
    }
}

// fragment-layout epi1: y1 = gelu(acc + aS[node] + aN[nbr]) -> tile A (bf16)
__device__ __forceinline__ void epi1_frag(u16* A, int ebase, const int* nbrS, int nbrBase,
                                          float acc[4][4][4],
                                          int wr0, int wc0, int gr, int ck) {
    uint32_t offS[8], offN[8];
    #pragma unroll
    for (int mi = 0; mi < 4; mi++)
        #pragma unroll
        for (int hh = 0; hh < 2; hh++) {
            int r = wr0 + mi * 16 + gr + hh * 8;
            int j = mi * 2 + hh;
            offS[j] = (uint32_t)(((ebase + r) / KNB) * CV) * 2;
            offN[j] = (uint32_t)(nbrS[nbrBase + r] * CV) * 2;
        }
    const char* aSb = (const char*)g_aS;
    const char* aNb = (const char*)g_aN;
    #pragma unroll
    for (int mi = 0; mi < 4; mi++)
        #pragma unroll
        for (int ni = 0; ni < 4; ni++) {
            int c = wc0 + ni * 8 + ck;
            #pragma unroll
            for (int hh = 0; hh < 2; hh++) {
                int j = mi * 2 + hh;
                unsigned as = *(const unsigned*)(aSb + offS[j] + c * 2);
                unsigned an = *(const unsigned*)(aNb + offN[j] + c * 2);
                float2 a = __bfloat1622float2(*(__nv_bfloat162*)&as);
                float2 n = __bfloat1622float2(*(__nv_bfloat162*)&an);
                float v0 = acc[mi][ni][2 * hh]     + a.x + n.x;
                float v1 = acc[mi][ni][2 * hh + 1] + a.y + n.y;
                int r = wr0 + mi * 16 + gr + hh * 8;
                *(__nv_bfloat162*)&A[r * STR + c] = bf2(gelu_f(v0), gelu_f(v1));
            }
        }
}

// ============================================================
// prep conversions
// ============================================================
__global__ void k_cvt3(const float* __restrict__ s2, const float* __restrict__ s3,
                       const float* __restrict__ s1full,
                       u16* __restrict__ d2, u16* __restrict__ d3, u16* __restrict__ d1e)
{
    int i = blockIdx.x * 256 + threadIdx.x;
    int seg = i >> 14, j = i & 16383;
    if (seg == 0)      d2[j] = __bfloat16_as_ushort(__float2bfloat16(s2[j]));
    else if (seg == 1) d3[j] = __bfloat16_as_ushort(__float2bfloat16(s3[j]));
    else {
        int o = j >> 7, c = j & 127;
        d1e[j] = __bfloat16_as_ushort(__float2bfloat16(s1full[o * IN_DIM + CV + c]));
    }
}
__global__ void k_cvtd(const float* __restrict__ w1, const float* __restrict__ w2)
{
    int i = blockIdx.x * 256 + threadIdx.x;
    if (i < 65536) g_dw1[i] = __bfloat16_as_ushort(__float2bfloat16(w1[i]));
    else           g_dw2[i - 65536] = __bfloat16_as_ushort(__float2bfloat16(w2[i - 65536]));
}

// ============================================================
// node precompute: aS (y=0) and aN (y=1) in one launch
// ============================================================
__global__ void __launch_bounds__(256, 2)
k_nodepre(const float* __restrict__ hVsrc, const float* __restrict__ w1,
          const float* __restrict__ b1)
{
    extern __shared__ char smx[];
    u16* Xs = (u16*)smx;
    u16* Ws = Xs + 128 * STR;
    const int tid = threadIdx.x;
    const int wp = tid >> 5, lane = tid & 31;
    const int wr0 = (wp & 1) * 64, wc0 = (wp >> 1) * 32;
    const int gr = lane >> 2, ck = (lane & 3) * 2;
    const int r0 = blockIdx.x * 128;
    const int cg = blockIdx.y;
    const int koff = cg ? 2 * CV : 0;
    u16* dst = cg ? g_aN : g_aS;

    for (int e = tid; e < 128 * 32; e += 256) {
        int r = e >> 5, q = e & 31;
        float4 v = *(const float4*)&hVsrc[(r0 + r) * CV + 4 * q];
        __nv_bfloat162 a = bf2(v.x, v.y), b = bf2(v.z, v.w);
        uint2 o = { *(unsigned*)&a, *(unsigned*)&b };
        *(uint2*)&Xs[r * STR + 4 * q] = o;
    }
    for (int e = tid; e < 128 * 32; e += 256) {
        int n = e >> 5, q = e & 31;
        float4 v = *(const float4*)&w1[n * IN_DIM + koff + 4 * q];
        __nv_bfloat162 a = bf2(v.x, v.y), b = bf2(v.z, v.w);
        uint2 o = { *(unsigned*)&a, *(unsigned*)&b };
        *(uint2*)&Ws[n * STR + 4 * q] = o;
    }
    __syncthreads();
    uint32_t aA = smem_u32(Xs) + ldsm_lane_off(lane, wr0);
    uint32_t bA = smem_u32(Ws) + ldsm_lane_off(lane, wc0);
    float acc[4][4][4];
    zero_acc(acc);
    #pragma unroll
    for (int ks = 0; ks < 8; ks++)
        mma_step(aA + ks * 32, bA + ks * 32, acc);
    #pragma unroll
    for (int mi = 0; mi < 4; mi++)
        #pragma unroll
        for (int ni = 0; ni < 4; ni++) {
            int r = wr0 + mi * 16 + gr, c = wc0 + ni * 8 + ck;
            float b0v = cg ? 0.f : b1[c], b1v = cg ? 0.f : b1[c + 1];
            *(__nv_bfloat162*)&dst[(r0 + r) * CV + c] = bf2(acc[mi][ni][0] + b0v, acc[mi][ni][1] + b1v);
            *(__nv_bfloat162*)&dst[(r0 + r + 8) * CV + c] = bf2(acc[mi][ni][2] + b0v, acc[mi][ni][3] + b1v);
        }
}

// ============================================================
// k_fused2 (message): 2-layer MLP, 256 edge rows / block (2 chunks),
// shared W buffer; epilogue reduces rows per node -> g_Spart.
// ============================================================
__global__ void __launch_bounds__(256, 2)
k_fused2(const float* __restrict__ hEf, const int* __restrict__ nbr,
         const u16* __restrict__ W1e, const u16* __restrict__ W2,
         const float* __restrict__ b2, const float* __restrict__ maskA)
{
    extern __shared__ char sm[];
    u16* A0 = (u16*)sm;
    u16* A1 = (u16*)(sm + TBYTES);
    __shared__ int nbrS[256];
    __shared__ float maS[256];

    const int tid = threadIdx.x;
    const int wp = tid >> 5, lane = tid & 31;
    const int wr0 = (wp & 1) * 64, wc0 = (wp >> 1) * 32;
    const int gr = lane >> 2, ck = (lane & 3) * 2;
    const int e0 = blockIdx.x * 256;

    const uint32_t smb = smem_u32(sm);
    const uint32_t A0_addr = smb + ldsm_lane_off(lane, wr0);
    const uint32_t A1_addr = smb + TBYTES + ldsm_lane_off(lane, wr0);
    const uint32_t W_addr  = smb + 2 * TBYTES + ldsm_lane_off(lane, wc0);
    const uint32_t W_base  = smb + 2 * TBYTES;

    stage_w_async(W_base, W1e, tid);
    CP_COMMIT();

    #pragma unroll
    for (int e = tid; e < 256 * 16; e += 256) {
        int r = e >> 4, q = e & 15;
        const float4* src = (const float4*)&hEf[(size_t)(e0 + r) * CV + q * 8];
        float4 v0 = src[0], v1 = src[1];
        __nv_bfloat162 p0 = bf2(v0.x, v0.y), p1 = bf2(v0.z, v0.w);
        __nv_bfloat162 p2 = bf2(v1.x, v1.y), p3 = bf2(v1.z, v1.w);
        uint4 o = { *(unsigned*)&p0, *(unsigned*)&p1, *(unsigned*)&p2, *(unsigned*)&p3 };
        u16* dst = (r < 128) ? &A0[r * STR + q * 8] : &A1[(r - 128) * STR + q * 8];
        *(uint4*)dst = o;
    }
    nbrS[tid] = nbr[e0 + tid];
    maS[tid]  = maskA[e0 + tid];
    CP_WAIT(0);
    __syncthreads();

    float acc[4][4][4];

    // layer 1, chunk 0
    zero_acc(acc);
    #pragma unroll
    for (int ks = 0; ks < 8; ks++)
        mma_step(A0_addr + ks * 32, W_addr + ks * 32, acc);
    __syncthreads();
    epi1_frag(A0, e0, nbrS, 0, acc, wr0, wc0, gr, ck);

    // layer 1, chunk 1
    zero_acc(acc);
    #pragma unroll
    for (int ks = 0; ks < 8; ks++)
        mma_step(A1_addr + ks * 32, W_addr + ks * 32, acc);
    __syncthreads();
    stage_w_async(W_base, W2, tid);
    CP_COMMIT();
    epi1_frag(A1, e0 + 128, nbrS, 128, acc, wr0, wc0, gr, ck);
    CP_WAIT(0);
    __syncthreads();

    // layer 2, chunk 0
    zero_acc(acc);
    #pragma unroll
    for (int ks = 0; ks < 8; ks++)
        mma_step(A0_addr + ks * 32, W_addr + ks * 32, acc);
    __syncthreads();
    #pragma unroll
    for (int mi = 0; mi < 4; mi++)
        #pragma unroll
        for (int ni = 0; ni < 4; ni++) {
            int r = wr0 + mi * 16 + gr, c = wc0 + ni * 8 + ck;
            float b0v = b2[c], b1v = b2[c + 1];
            float ma1 = maS[r], ma2 = maS[r + 8];
            *(__nv_bfloat162*)&A0[r * STR + c] =
                bf2(gelu_f(acc[mi][ni][0] + b0v) * ma1, gelu_f(acc[mi][ni][1] + b1v) * ma1);
            *(__nv_bfloat162*)&A0[(r + 8) * STR + c] =
                bf2(gelu_f(acc[mi][ni][2] + b0v) * ma2, gelu_f(acc[mi][ni][3] + b1v) * ma2);
        }

    // layer 2, chunk 1
    zero_acc(acc);
    #pragma unroll
    for (int ks = 0; ks < 8; ks++)
        mma_step(A1_addr + ks * 32, W_addr + ks * 32, acc);
    __syncthreads();
    #pragma unroll
    for (int mi = 0; mi < 4; mi++)
        #pragma unroll
        for (int ni = 0; ni < 4; ni++) {
            int r = wr0 + mi * 16 + gr, c = wc0 + ni * 8 + ck;
            float b0v = b2[c], b1v = b2[c + 1];
            float ma1 = maS[128 + r], ma2 = maS[128 + r + 8];
            *(__nv_bfloat162*)&A1[r * STR + c] =
                bf2(gelu_f(acc[mi][ni][0] + b0v) * ma1, gelu_f(acc[mi][ni][1] + b1v) * ma1);
            *(__nv_bfloat162*)&A1[(r + 8) * STR + c] =
                bf2(gelu_f(acc[mi][ni][2] + b0v) * ma2, gelu_f(acc[mi][ni][3] + b1v) * ma2);
        }
    __syncthreads();

    // reduce per node segment -> g_Spart
    {
        int nd0 = e0 / KNB;
        int ndLast = (e0 + 255) / KNB;
        int nSeg = ndLast - nd0 + 1;
        for (int sc = tid; sc < nSeg * CV; sc += 256) {
            int seg = sc >> 7, c = sc & 127;
            int n = nd0 + seg;
            int rlo = n * KNB;       if (rlo < e0) rlo = e0;
            int rhi = n * KNB + KNB; if (rhi > e0 + 256) rhi = e0 + 256;
            float s = 0.f;
            int l0 = rlo - e0, l1 = rhi - e0;
            int m0 = l1 < 128 ? l1 : 128;
            for (int r = l0; r < m0; r++)
                s += __bfloat162float(*(const __nv_bfloat16*)&A0[r * STR + c]);
            int m1 = l0 > 128 ? l0 : 128;
            for (int r = m1; r < l1; r++)
                s += __bfloat162float(*(const __nv_bfloat16*)&A1[(r - 128) * STR + c]);
            int slot = (e0 >> 8) - ((n * KNB) >> 8);
            g_Spart[((size_t)n * 2 + slot) * CV + c] = s;
        }
    }
}

// ============================================================
// k_msgfin: dh = (W3 @ S + (Σma)·b3)/30; g_v1 = LN1(hV + dh)
// ============================================================
__global__ void __launch_bounds__(256, 2)
k_msgfin(const float* __restrict__ hV, const float* __restrict__ b3,
         const float* __restrict__ lnw, const float* __restrict__ lnb,
         const float* __restrict__ maskA)
{
    extern __shared__ char smx[];
    u16* Xs = (u16*)smx;
    float* Zf = (float*)smx;
    __shared__ float smaS[128];
    const uint32_t smb = smem_u32(smx);
    const int tid = threadIdx.x;
    const int wp = tid >> 5, lane = tid & 31;
    const int wr0 = (wp & 1) * 64, wc0 = (wp >> 1) * 32;
    const int gr = lane >> 2, ck = (lane & 3) * 2;
    const int r0 = blockIdx.x * 128;

    stage_w_async(smb + TBYTES, g_w3m, tid);
    CP_COMMIT();

    {
        int r = tid >> 1, h = tid & 1;
        const float* mp = &maskA[(r0 + r) * KNB + h * 24];
        float s = 0.f;
        #pragma unroll
        for (int i = 0; i < 24; i++) s += mp[i];
        s += __shfl_xor_sync(0xffffffffu, s, 1);
        if (h == 0) smaS[r] = s;
    }

    for (int e = tid; e < 128 * 32; e += 256) {
        int r = e >> 5, q = e & 31;
        int n = r0 + r;
        float4 v = *(const float4*)&g_Spart[(size_t)n * 2 * CV + 4 * q];
        if (((n * KNB) & 255) >= 209) {
            float4 w = *(const float4*)&g_Spart[((size_t)n * 2 + 1) * CV + 4 * q];
            v.x += w.x; v.y += w.y; v.z += w.z; v.w += w.w;
        }
        __nv_bfloat162 a = bf2(v.x, v.y), bb = bf2(v.z, v.w);
        uint2 o = { *(unsigned*)&a, *(unsigned*)&bb };
        *(uint2*)&Xs[r * STR + 4 * q] = o;
    }
    CP_WAIT(0);
    __syncthreads();

    uint32_t aA = smb + ldsm_lane_off(lane, wr0);
    uint32_t bA = smb + TBYTES + ldsm_lane_off(lane, wc0);
    float acc[4][4][4];
    zero_acc(acc);
    #pragma unroll
    for (int ks = 0; ks < 8; ks++)
        mma_step(aA + ks * 32, bA + ks * 32, acc);
    __syncthreads();

    #pragma unroll
    for (int mi = 0; mi < 4; mi++)
        #pragma unroll
        for (int ni = 0; ni < 4; ni++) {
            int r = wr0 + mi * 16 + gr, c = wc0 + ni * 8 + ck;
            float b0v = b3[c], b1v = b3[c + 1];
            float sm1 = smaS[r], sm2 = smaS[r + 8];
            float2 h1 = *(const float2*)&hV[(r0 + r) * CV + c];
            float2 h2 = *(const float2*)&hV[(r0 + r + 8) * CV + c];
            *(float2*)&Zf[r * Z_STR + c] = make_float2(
                h1.x + (acc[mi][ni][0] + sm1 * b0v) * (1.0f / 30.0f),
                h1.y + (acc[mi][ni][1] + sm1 * b1v) * (1.0f / 30.0f));
            *(float2*)&Zf[(r + 8) * Z_STR + c] = make_float2(
                h2.x + (acc[mi][ni][2] + sm2 * b0v) * (1.0f / 30.0f),
                h2.y + (acc[mi][ni][3] + sm2 * b1v) * (1.0f / 30.0f));
        }
    __syncthreads();
    {
        int r = tid >> 1, h = tid & 1;
        float s = 0.f, sq = 0.f;
        #pragma unroll 8
        for (int c = h * 64; c < h * 64 + 64; c++) {
            float v = Zf[r * Z_STR + c];
            s += v; sq += v * v;
        }
        s  += __shfl_xor_sync(0xffffffffu, s, 1);
        sq += __shfl_xor_sync(0xffffffffu, sq, 1);
        float mean = s * (1.0f / CV);
        float var  = sq * (1.0f / CV) - mean * mean;
        float inv  = rsqrtf(var + LN_EPS);
        for (int c = h * 64; c < h * 64 + 64; c++) {
            float v = Zf[r * Z_STR + c];
            g_v1[(r0 + r) * CV + c] = (v - mean) * inv * lnw[c] + lnb[c];
        }
    }
}

// ============================================================
// k_fused3 (edge update): 3-layer MLP + residual + fragment-resident LN3
// ============================================================
__global__ void __launch_bounds__(256, 2)
k_fused3(const float* __restrict__ hEf, const int* __restrict__ nbr,
         const u16* __restrict__ W1e, const u16* __restrict__ W2, const u16* __restrict__ W3,
         const float* __restrict__ b2, const float* __restrict__ b3,
         const float* __restrict__ lnw, const float* __restrict__ lnb,
         float* __restrict__ outE)
{
    extern __shared__ char sm[];
    u16* B0 = (u16*)sm;
    __shared__ int nbrS[128];
    __shared__ float redS[128 * 4];
    __shared__ float redQ[128 * 4];

    const int tid = threadIdx.x;
    const int wp = tid >> 5, lane = tid & 31;
    const int wr0 = (wp & 1) * 64, wc0 = (wp >> 1) * 32;
    const int gr = lane >> 2, ck = (lane & 3) * 2;
    const int e0 = blockIdx.x * 128;

    const uint32_t smb = smem_u32(sm);
    const uint32_t A_addr  = smb + ldsm_lane_off(lane, wr0);
    const uint32_t B1_addr = smb + TBYTES + ldsm_lane_off(lane, wc0);
    const uint32_t B2_addr = smb + 2 * TBYTES + ldsm_lane_off(lane, wc0);

    stage_w_async(smb + TBYTES, W1e, tid);
    CP_COMMIT();
    stage_w_async(smb + 2 * TBYTES, W2, tid);
    CP_COMMIT();

    #pragma unroll
    for (int e = tid; e < 128 * 16; e += 256) {
        int r = e >> 4, q = e & 15;
        const float4* src = (const float4*)&hEf[(size_t)(e0 + r) * CV + q * 8];
        float4 v0 = src[0], v1 = src[1];
        __nv_bfloat162 p0 = bf2(v0.x, v0.y), p1 = bf2(v0.z, v0.w);
        __nv_bfloat162 p2 = bf2(v1.x, v1.y), p3 = bf2(v1.z, v1.w);
        uint4 o = { *(unsigned*)&p0, *(unsigned*)&p1, *(unsigned*)&p2, *(unsigned*)&p3 };
        *(uint4*)&B0[r * STR + q * 8] = o;
    }
    if (tid < 128) nbrS[tid] = nbr[e0 + tid];
    CP_WAIT(1);
    __syncthreads();

    float acc[4][4][4];
    zero_acc(acc);
    #pragma unroll
    for (int ks = 0; ks < 8; ks++)
        mma_step(A_addr + ks * 32, B1_addr + ks * 32, acc);
    __syncthreads();

    epi1_frag(B0, e0, nbrS, 0, acc, wr0, wc0, gr, ck);
    stage_w_async(smb + TBYTES, W3, tid);
    CP_COMMIT();
    CP_WAIT(1);
    __syncthreads();

    zero_acc(acc);
    #pragma unroll
    for (int ks = 0; ks < 8; ks++)
        mma_step(A_addr + ks * 32, B2_addr + ks * 32, acc);
    __syncthreads();
    #pragma unroll
    for (int mi = 0; mi < 4; mi++)
        #pragma unroll
        for (int ni = 0; ni < 4; ni++) {
            int r = wr0 + mi * 16 + gr, c = wc0 + ni * 8 + ck;
            float b0v = b2[c], b1v = b2[c + 1];
            *(__nv_bfloat162*)&B0[r * STR + c] =
                bf2(gelu_f(acc[mi][ni][0] + b0v), gelu_f(acc[mi][ni][1] + b1v));
            *(__nv_bfloat162*)&B0[(r + 8) * STR + c] =
                bf2(gelu_f(acc[mi][ni][2] + b0v), gelu_f(acc[mi][ni][3] + b1v));
        }
    CP_WAIT(0);
    __syncthreads();

    zero_acc(acc);
    #pragma unroll
    for (int ks = 0; ks < 8; ks++)
        mma_step(A_addr + ks * 32, B1_addr + ks * 32, acc);

    // ---- fragment-resident LN3 ----
    // z = acc + b3 + residual (kept in acc); row stats via quad-shfl + smem
    float sP[4][2], qP[4][2];
    #pragma unroll
    for (int mi = 0; mi < 4; mi++)
        #pragma unroll
        for (int hh = 0; hh < 2; hh++) { sP[mi][hh] = 0.f; qP[mi][hh] = 0.f; }
    #pragma unroll
    for (int mi = 0; mi < 4; mi++)
        #pragma unroll
        for (int ni = 0; ni < 4; ni++) {
            int c = wc0 + ni * 8 + ck;
            float b0v = b3[c], b1v = b3[c + 1];
            int r1 = wr0 + mi * 16 + gr;
            float2 res1 = *(const float2*)&hEf[(size_t)(e0 + r1) * CV + c];
            float2 res2 = *(const float2*)&hEf[(size_t)(e0 + r1 + 8) * CV + c];
            acc[mi][ni][0] += b0v + res1.x;
            acc[mi][ni][1] += b1v + res1.y;
            acc[mi][ni][2] += b0v + res2.x;
            acc[mi][ni][3] += b1v + res2.y;
            sP[mi][0] += acc[mi][ni][0] + acc[mi][ni][1];
            qP[mi][0] += acc[mi][ni][0] * acc[mi][ni][0] + acc[mi][ni][1] * acc[mi][ni][1];
            sP[mi][1] += acc[mi][ni][2] + acc[mi][ni][3];
            qP[mi][1] += acc[mi][ni][2] * acc[mi][ni][2] + acc[mi][ni][3] * acc[mi][ni][3];
        }
    #pragma unroll
    for (int mi = 0; mi < 4; mi++)
        #pragma unroll
        for (int hh = 0; hh < 2; hh++) {
            sP[mi][hh] += __shfl_xor_sync(0xffffffffu, sP[mi][hh], 1);
            sP[mi][hh] += __shfl_xor_sync(0xffffffffu, sP[mi][hh], 2);
            qP[mi][hh] += __shfl_xor_sync(0xffffffffu, qP[mi][hh], 1);
            qP[mi][hh] += __shfl_xor_sync(0xffffffffu, qP[mi][hh], 2);
        }
    {
        int wc = wp >> 1;
        if ((lane & 3) == 0) {
            #pragma unroll
            for (int mi = 0; mi < 4; mi++)
                #pragma unroll
                for (int hh = 0; hh < 2; hh++) {
                    int r = wr0 + mi * 16 + gr + hh * 8;
                    redS[r * 4 + wc] = sP[mi][hh];
                    redQ[r * 4 + wc] = qP[mi][hh];
                }
        }
    }
    __syncthreads();
    float meanR[4][2], invR[4][2];
    #pragma unroll
    for (int mi = 0; mi < 4; mi++)
        #pragma unroll
        for (int hh = 0; hh < 2; hh++) {
            int r = wr0 + mi * 16 + gr + hh * 8;
            float s = redS[r * 4] + redS[r * 4 + 1] + redS[r * 4 + 2] + redS[r * 4 + 3];
            float q = redQ[r * 4] + redQ[r * 4 + 1] + redQ[r * 4 + 2] + redQ[r * 4 + 3];
            float mean = s * (1.0f / CV);
            float var  = q * (1.0f / CV) - mean * mean;
            meanR[mi][hh] = mean;
            invR[mi][hh]  = rsqrtf(var + LN_EPS);
        }
    #pragma unroll
    for (int mi = 0; mi < 4; mi++)
        #pragma unroll
        for (int ni = 0; ni < 4; ni++) {
            int c = wc0 + ni * 8 + ck;
            float2 wv = *(const float2*)&lnw[c];
            float2 bv = *(const float2*)&lnb[c];
            int r1 = wr0 + mi * 16 + gr;
            float2 o1 = make_float2(
                (acc[mi][ni][0] - meanR[mi][0]) * invR[mi][0] * wv.x + bv.x,
                (acc[mi][ni][1] - meanR[mi][0]) * invR[mi][0] * wv.y + bv.y);
            float2 o2 = make_float2(
                (acc[mi][ni][2] - meanR[mi][1]) * invR[mi][1] * wv.x + bv.x,
                (acc[mi][ni][3] - meanR[mi][1]) * invR[mi][1] * wv.y + bv.y);
            *(float2*)&outE[(size_t)(e0 + r1) * CV + c] = o1;
            *(float2*)&outE[(size_t)(e0 + r1 + 8) * CV + c] = o2;
        }
}

// ============================================================
// dense1
// ============================================================
__global__ void __launch_bounds__(256, 2)
k_dense1(const float* __restrict__ b)
{
    extern __shared__ char smx[];
    u16* Xs = (u16*)smx;
    const uint32_t smb = smem_u32(smx);
    const int tid = threadIdx.x;
    const int wp = tid >> 5, lane = tid & 31;
    const int wr0 = (wp & 1) * 64, wc0 = (wp >> 1) * 32;
    const int gr = lane >> 2, ck = (lane & 3) * 2;
    const int r0 = blockIdx.x * 128, c0 = blockIdx.y * 128;

    stage_w_async(smb + TBYTES, &g_dw1[c0 * CV], tid);
    CP_COMMIT();
    for (int e = tid; e < 128 * 32; e += 256) {
        int r = e >> 5, q = e & 31;
        float4 v = *(const float4*)&g_v1[(r0 + r) * CV + 4 * q];
        __nv_bfloat162 a = bf2(v.x, v.y), bb = bf2(v.z, v.w);
        uint2 o = { *(unsigned*)&a, *(unsigned*)&bb };
        *(uint2*)&Xs[r * STR + 4 * q] = o;
    }
    CP_WAIT(0);
    __syncthreads();
    uint32_t aA = smb + ldsm_lane_off(lane, wr0);
    uint32_t bA = smb + TBYTES + ldsm_lane_off(lane, wc0);
    float acc[4][4][4];
    zero_acc(acc);
    #pragma unroll
    for (int ks = 0; ks < 8; ks++)
        mma_step(aA + ks * 32, bA + ks * 32, acc);
    #pragma unroll
    for (int mi = 0; mi < 4; mi++)
        #pragma unroll
        for (int ni = 0; ni < 4; ni++) {
            int r = wr0 + mi * 16 + gr, cg = c0 + wc0 + ni * 8 + ck;
            float b0v = b[cg], b1v = b[cg + 1];
            *(__nv_bfloat162*)&g_yd[(size_t)(r0 + r) * DW + cg] =
                bf2(gelu_f(acc[mi][ni][0] + b0v), gelu_f(acc[mi][ni][1] + b1v));
            *(__nv_bfloat162*)&g_yd[(size_t)(r0 + r + 8) * DW + cg] =
                bf2(gelu_f(acc[mi][ni][2] + b0v), gelu_f(acc[mi][ni][3] + b1v));
        }
}

// ============================================================
// dense2
// ============================================================
__device__ __forceinline__ void d2_stage(uint32_t pairBase, int r0, int kt, int tid) {
    #pragma unroll
    for (int e = tid; e < 2048; e += 256) {
        int r = e >> 4, q = e & 15;
        cp16(pairBase + (uint32_t)(r * STR + q * 8) * 2,
             &g_yd[(size_t)(r0 + r) * DW + kt + q * 8]);
    }
    #pragma unroll
    for (int e = tid; e < 2048; e += 256) {
        int n = e >> 4, q = e & 15;
        cp16(pairBase + TBYTES + (uint32_t)(n * STR + q * 8) * 2,
             &g_dw2[n * DW + kt + q * 8]);
    }
    CP_COMMIT();
}

__global__ void __launch_bounds__(256, 1)
k_dense2(const float* __restrict__ b,
         const float* __restrict__ lnw, const float* __restrict__ lnb,
         const float* __restrict__ mask, float* __restrict__ outV)
{
    extern __shared__ char smx[];
    float* Zf = (float*)smx;
    const uint32_t smb = smem_u32(smx);
    const int tid = threadIdx.x;
    const int wp = tid >> 5, lane = tid & 31;
    const int wr0 = (wp & 1) * 64, wc0 = (wp >> 1) * 32;
    const int gr = lane >> 2, ck = (lane & 3) * 2;
    const int r0 = blockIdx.x * 128;

    float acc[4][4][4];
    zero_acc(acc);
    d2_stage(smb, r0, 0, tid);
    #pragma unroll
    for (int i = 0; i < 4; i++) {
        if (i < 3) d2_stage(smb + ((i + 1) & 1) * 2 * TBYTES, r0, (i + 1) * 128, tid);
        if (i < 3) { CP_WAIT(1); } else { CP_WAIT(0); }
        __syncthreads();
        uint32_t pb = smb + (i & 1) * 2 * TBYTES;
        uint32_t aA = pb + ldsm_lane_off(lane, wr0);
        uint32_t bA = pb + TBYTES + ldsm_lane_off(lane, wc0);
        #pragma unroll
        for (int ks = 0; ks < 8; ks++)
            mma_step(aA + ks * 32, bA + ks * 32, acc);
        __syncthreads();
    }
    #pragma unroll
    for (int mi = 0; mi < 4; mi++)
        #pragma unroll
        for (int ni = 0; ni < 4; ni++) {
            int r = wr0 + mi * 16 + gr, c = wc0 + ni * 8 + ck;
            float b0v = b[c], b1v = b[c + 1];
            float2 res1 = *(const float2*)&g_v1[(r0 + r) * CV + c];
            float2 res2 = *(const float2*)&g_v1[(r0 + r + 8) * CV + c];
            *(float2*)&Zf[r * Z_STR + c] =
                make_float2(acc[mi][ni][0] + b0v + res1.x, acc[mi][ni][1] + b1v + res1.y);
            *(float2*)&Zf[(r + 8) * Z_STR + c] =
                make_float2(acc[mi][ni][2] + b0v + res2.x, acc[mi][ni][3] + b1v + res2.y);
        }
    __syncthreads();
    {
        int r = tid >> 1, h = tid & 1;
        float s = 0.f, sq = 0.f;
        #pragma unroll 8
        for (int c = h * 64; c < h * 64 + 64; c++) {
            float v = Zf[r * Z_STR + c];
            s += v; sq += v * v;
        }
        s  += __shfl_xor_sync(0xffffffffu, s, 1);
        sq += __shfl_xor_sync(0xffffffffu, sq, 1);
        float mean = s * (1.0f / CV);
        float var  = sq * (1.0f / CV) - mean * mean;
        float inv  = rsqrtf(var + LN_EPS);
        float mk = mask[r0 + r];
        for (int c = h * 64; c < h * 64 + 64; c++) {
            float v = Zf[r * Z_STR + c];
            outV[(r0 + r) * CV + c] = ((v - mean) * inv * lnw[c] + lnb[c]) * mk;
        }
    }
}

// ============================================================
extern "C" void kernel_launch(void* const* d_in, const int* in_sizes, int n_in,
                              void* d_out, int out_size)
{
    (void)in_sizes; (void)n_in; (void)out_size;
    const float* hV    = (const float*)d_in[0];
    const float* hE    = (const float*)d_in[1];
    const int*   nbr   = (const int*)  d_in[2];
    const float* mask  = (const float*)d_in[3];
    const float* maskA = (const float*)d_in[4];
    const float* msg_w1 = (const float*)d_in[5];
    const float* msg_b1 = (const float*)d_in[6];
    const float* msg_w2 = (const float*)d_in[7];
    const float* msg_b2 = (const float*)d_in[8];
    const float* msg_w3 = (const float*)d_in[9];
    const float* msg_b3 = (const float*)d_in[10];
    const float* ln1_w  = (const float*)d_in[11];
    const float* ln1_b  = (const float*)d_in[12];
    const float* d_w1   = (const float*)d_in[13];
    const float* d_b1   = (const float*)d_in[14];
    const float* d_w2   = (const float*)d_in[15];
    const float* d_b2   = (const float*)d_in[16];
    const float* ln2_w  = (const float*)d_in[17];
    const float* ln2_b  = (const float*)d_in[18];
    const float* eu_w1  = (const float*)d_in[19];
    const float* eu_b1  = (const float*)d_in[20];
    const float* eu_w2  = (const float*)d_in[21];
    const float* eu_b2  = (const float*)d_in[22];
    const float* eu_w3  = (const float*)d_in[23];
    const float* eu_b3  = (const float*)d_in[24];
    const float* ln3_w  = (const float*)d_in[25];
    const float* ln3_b  = (const float*)d_in[26];

    float* outV = (float*)d_out;
    float* outE = outV + (size_t)N_NODES * CV;

    u16 *p_w2m, *p_w3m, *p_w2e, *p_w3e, *p_w1em, *p_w1ee;
    cudaGetSymbolAddress((void**)&p_w2m, g_w2m);
    cudaGetSymbolAddress((void**)&p_w3m, g_w3m);
    cudaGetSymbolAddress((void**)&p_w2e, g_w2e);
    cudaGetSymbolAddress((void**)&p_w3e, g_w3e);
    cudaGetSymbolAddress((void**)&p_w1em, g_w1em);
    cudaGetSymbolAddress((void**)&p_w1ee, g_w1ee);

    const int SMEM_F  = 3 * TBYTES;   // 104448
    const int SMEM_G  = 2 * TBYTES;   // 69632
    const int SMEM_D2 = 4 * TBYTES;   // 139264
    cudaFuncSetAttribute(k_fused2,  cudaFuncAttributeMaxDynamicSharedMemorySize, SMEM_F);
    cudaFuncSetAttribute(k_fused3,  cudaFuncAttributeMaxDynamicSharedMemorySize, SMEM_F);
    cudaFuncSetAttribute(k_msgfin,  cudaFuncAttributeMaxDynamicSharedMemorySize, SMEM_G);
    cudaFuncSetAttribute(k_nodepre, cudaFuncAttributeMaxDynamicSharedMemorySize, SMEM_G);
    cudaFuncSetAttribute(k_dense1,  cudaFuncAttributeMaxDynamicSharedMemorySize, SMEM_G);
    cudaFuncSetAttribute(k_dense2,  cudaFuncAttributeMaxDynamicSharedMemorySize, SMEM_D2);

    k_cvt3<<<192, 256>>>(msg_w2, msg_w3, msg_w1, p_w2m, p_w3m, p_w1em);
    k_cvt3<<<192, 256>>>(eu_w2,  eu_w3,  eu_w1,  p_w2e, p_w3e, p_w1ee);
    k_cvtd<<<512, 256>>>(d_w1, d_w2);
    k_nodepre<<<dim3(N_NODES / 128, 2), 256, SMEM_G>>>(hV, msg_w1, msg_b1);
    k_fused2<<<EDGES / 256, 256, SMEM_F>>>(hE, nbr, p_w1em, p_w2m, msg_b2, maskA);
    k_msgfin<<<N_NODES / 128, 256, SMEM_G>>>(hV, msg_b3, ln1_w, ln1_b, maskA);
    k_dense1<<<dim3(N_NODES / 128, 4), 256, SMEM_G>>>(d_b1);
    k_dense2<<<N_NODES / 128, 256, SMEM_D2>>>(d_b2, ln2_w, ln2_b, mask, outV);
    k_nodepre<<<dim3(N_NODES / 128, 2), 256, SMEM_G>>>(outV, eu_w1, eu_b1);
    k_fused3<<<EDGES / 128, 256, SMEM_F>>>(hE, nbr, p_w1ee, p_w2e, p_w3e,
                                           eu_b2, eu_b3, ln3_w, ln3_b, outE);
}